// round 1
// baseline (speedup 1.0000x reference)
#include <cuda_runtime.h>

#define BB 4
#define CF 256
#define CC 64
#define HH 128
#define WW 128
#define CP 80
#define PH 64
#define PW 64
#define KS 5
#define KK 25

// scratch (no allocations allowed)
__device__ float g_guide[BB * CC * HH * WW];   // 16.7 MB
__device__ float g_mask[BB * KK * HH * WW];    // 6.5 MB

__device__ __forceinline__ int refl(int v, int n) {
    v = (v < 0) ? -v : v;
    v = (v >= n) ? (2 * n - 2 - v) : v;
    return v;
}

// ---------------------------------------------------------------------------
// Kernel 1: guide[b][o][p] = sum_c w[o][c] * feat[b][c][p] + bias[o]
// Per batch: M=64, K=256, N=16384. Block tile 64x128, 256 threads, 8x4/thread.
// ---------------------------------------------------------------------------
__global__ void compress_kernel(const float* __restrict__ feat,
                                const float* __restrict__ wc,
                                const float* __restrict__ bc) {
    __shared__ float As[16][68];    // [kk][o], padded for alignment
    __shared__ float Bs[16][128];   // [kk][n]

    int b  = blockIdx.y;
    int p0 = blockIdx.x * 128;
    int tid = threadIdx.x;
    int tm = tid >> 5;    // 0..7  (same for whole warp -> broadcast A reads)
    int tn = tid & 31;    // 0..31
    int m0 = tm * 8;
    int n0 = tn * 4;

    float acc[8][4];
#pragma unroll
    for (int i = 0; i < 8; i++)
#pragma unroll
        for (int j = 0; j < 4; j++) acc[i][j] = 0.f;

    const float* fb = feat + (size_t)b * CF * HH * WW + p0;

    for (int k0 = 0; k0 < CF; k0 += 16) {
        // A chunk: 64 x 16 = 1024 elems
#pragma unroll
        for (int t = 0; t < 4; t++) {
            int i = tid + t * 256;
            int o  = i >> 4;
            int kk = i & 15;
            As[kk][o] = wc[o * CF + k0 + kk];
        }
        // B chunk: 16 x 128 = 2048 elems (coalesced rows)
#pragma unroll
        for (int t = 0; t < 8; t++) {
            int i = tid + t * 256;
            int kk = i >> 7;
            int n  = i & 127;
            Bs[kk][n] = fb[(size_t)(k0 + kk) * (HH * WW) + n];
        }
        __syncthreads();

#pragma unroll
        for (int kk = 0; kk < 16; kk++) {
            float4 a0 = *(const float4*)&As[kk][m0];
            float4 a1 = *(const float4*)&As[kk][m0 + 4];
            float4 b4 = *(const float4*)&Bs[kk][n0];
            float a[8] = {a0.x, a0.y, a0.z, a0.w, a1.x, a1.y, a1.z, a1.w};
            float bv[4] = {b4.x, b4.y, b4.z, b4.w};
#pragma unroll
            for (int i = 0; i < 8; i++)
#pragma unroll
                for (int j = 0; j < 4; j++)
                    acc[i][j] += a[i] * bv[j];
        }
        __syncthreads();
    }

    float* gb = g_guide + (size_t)b * CC * HH * WW + p0;
#pragma unroll
    for (int i = 0; i < 8; i++) {
        float bias = bc[m0 + i];
        float4 v = make_float4(acc[i][0] + bias, acc[i][1] + bias,
                               acc[i][2] + bias, acc[i][3] + bias);
        *(float4*)&gb[(size_t)(m0 + i) * (HH * WW) + n0] = v;
    }
}

// ---------------------------------------------------------------------------
// Kernel 2: 3x3 conv (guide 64ch -> 25ch, SAME/zero pad) + bias + softmax(25)
// Block = 16x8 pixels, thread-per-pixel, 25(pad 28) accumulators.
// ---------------------------------------------------------------------------
__global__ void conv_softmax_kernel(const float* __restrict__ we,
                                    const float* __restrict__ be) {
    __shared__ float gs[16][10][18];   // c-chunk x (8+2) rows x (16+2) cols
    __shared__ float ws[16][9][28];    // c-chunk x tap x out(25 pad 28)

    int b  = blockIdx.z;
    int x0 = blockIdx.x * 16;
    int y0 = blockIdx.y * 8;
    int lx = threadIdx.x;
    int ly = threadIdx.y;
    int tid = ly * 16 + lx;

    float acc[28];
#pragma unroll
    for (int o = 0; o < 28; o++) acc[o] = 0.f;

    const float* gbase = g_guide + (size_t)b * CC * HH * WW;

    for (int c0 = 0; c0 < CC; c0 += 16) {
        // guide tile with halo, zero pad at borders
        for (int i = tid; i < 16 * 10 * 18; i += 128) {
            int cc  = i / 180;
            int r   = (i / 18) % 10;
            int col = i % 18;
            int gy = y0 + r - 1;
            int gx = x0 + col - 1;
            float v = 0.f;
            if (gy >= 0 && gy < HH && gx >= 0 && gx < WW)
                v = gbase[(size_t)(c0 + cc) * (HH * WW) + gy * WW + gx];
            gs[cc][r][col] = v;
        }
        // weight chunk: w_enc[o][c][ty][tx] -> ws[cc][tap][o]
        for (int i = tid; i < 25 * 16 * 9; i += 128) {
            int o   = i / 144;
            int cc  = (i / 9) % 16;
            int tap = i % 9;
            ws[cc][tap][o] = we[((o * CC + c0 + cc) * 9) + tap];
        }
        __syncthreads();

#pragma unroll
        for (int cc = 0; cc < 16; cc++) {
#pragma unroll
            for (int ty = 0; ty < 3; ty++) {
#pragma unroll
                for (int tx = 0; tx < 3; tx++) {
                    float g = gs[cc][ly + ty][lx + tx];
                    const float4* w4 = (const float4*)&ws[cc][ty * 3 + tx][0];
#pragma unroll
                    for (int o4 = 0; o4 < 7; o4++) {
                        float4 w = w4[o4];
                        acc[o4 * 4 + 0] += g * w.x;
                        acc[o4 * 4 + 1] += g * w.y;
                        acc[o4 * 4 + 2] += g * w.z;
                        acc[o4 * 4 + 3] += g * w.w;
                    }
                }
            }
        }
        __syncthreads();
    }

    // bias + softmax over the 25 real channels
    float m = -1e30f;
#pragma unroll
    for (int o = 0; o < 25; o++) {
        acc[o] += be[o];
        m = fmaxf(m, acc[o]);
    }
    float s = 0.f;
#pragma unroll
    for (int o = 0; o < 25; o++) {
        acc[o] = __expf(acc[o] - m);
        s += acc[o];
    }
    float inv = 1.f / s;
    float* mb = g_mask + (size_t)b * KK * HH * WW + (y0 + ly) * WW + (x0 + lx);
#pragma unroll
    for (int o = 0; o < 25; o++) mb[(size_t)o * (HH * WW)] = acc[o] * inv;
}

// ---------------------------------------------------------------------------
// Kernel 3: CARAFE reassembly.
// out[b][cp][Y][X] = sum_{i,j} pred_reflectpad[b][cp][Y/2+i][X/2+j]
//                              * mask[b][i*5+j][Y][X]
// Block = 32x8 output pixels; mask cached in 25 regs, reused over 80 channels;
// pred tile (8 rows x 20 cols) staged in smem per channel.
// ---------------------------------------------------------------------------
__global__ void carafe_kernel(const float* __restrict__ pred,
                              float* __restrict__ out) {
    __shared__ float ps[8][20];

    int b  = blockIdx.z;
    int X0 = blockIdx.x * 32;
    int Y0 = blockIdx.y * 8;
    int lx = threadIdx.x & 31;
    int ly = threadIdx.x >> 5;
    int X = X0 + lx;
    int Y = Y0 + ly;

    float mreg[25];
    const float* mb = g_mask + (size_t)b * KK * HH * WW + Y * WW + X;
#pragma unroll
    for (int o = 0; o < 25; o++) mreg[o] = mb[(size_t)o * (HH * WW)];

    int yin0 = Y0 / 2 - 2;
    int xin0 = X0 / 2 - 2;
    int py = (Y >> 1) - (Y0 >> 1);  // 0..3
    int px = (X >> 1) - (X0 >> 1);  // 0..15

    // per-thread smem fill coordinates (first 160 threads)
    int fr = threadIdx.x / 20;
    int fc = threadIdx.x % 20;
    int gy = refl(yin0 + fr, PH);
    int gx = refl(xin0 + fc, PW);

    const float* pb = pred + (size_t)b * CP * PH * PW;
    float* ob = out + (size_t)b * CP * HH * WW + Y * WW + X;

    for (int cp = 0; cp < CP; cp++) {
        if (threadIdx.x < 160)
            ps[fr][fc] = pb[(size_t)cp * PH * PW + gy * PW + gx];
        __syncthreads();

        float s = 0.f;
#pragma unroll
        for (int i = 0; i < 5; i++)
#pragma unroll
            for (int j = 0; j < 5; j++)
                s += ps[py + i][px + j] * mreg[i * 5 + j];

        ob[(size_t)cp * HH * WW] = s;
        __syncthreads();
    }
}

extern "C" void kernel_launch(void* const* d_in, const int* in_sizes, int n_in,
                              void* d_out, int out_size) {
    const float* pred = (const float*)d_in[0];
    const float* feat = (const float*)d_in[1];
    const float* wc   = (const float*)d_in[2];
    const float* bc   = (const float*)d_in[3];
    const float* we   = (const float*)d_in[4];
    const float* be   = (const float*)d_in[5];
    float* out = (float*)d_out;

    compress_kernel<<<dim3(HH * WW / 128, BB), 256>>>(feat, wc, bc);
    conv_softmax_kernel<<<dim3(WW / 16, HH / 8, BB), dim3(16, 8)>>>(we, be);
    carafe_kernel<<<dim3(WW / 32, HH / 8, BB), 256>>>(pred, out);
}

// round 2
// speedup vs baseline: 1.0710x; 1.0710x over previous
#include <cuda_runtime.h>

#define BB 4
#define CF 256
#define CC 64
#define HH 128
#define WW 128
#define HW (HH * WW)
#define CP 80
#define PH 64
#define PW 64
#define KS 5
#define KK 25

typedef unsigned long long ull;

// scratch (no allocations allowed)
__device__ float g_guide[BB * CC * HW];   // 16.7 MB
__device__ float g_mask[BB * KK * HW];    // 6.5 MB

__device__ __forceinline__ int refl(int v, int n) {
    v = (v < 0) ? -v : v;
    v = (v >= n) ? (2 * n - 2 - v) : v;
    return v;
}

__device__ __forceinline__ void ffma2(ull& d, ull a, ull b) {
    asm("fma.rn.f32x2 %0, %1, %2, %3;" : "=l"(d) : "l"(a), "l"(b), "l"(d));
}
__device__ __forceinline__ ull pack2(float x, float y) {
    ull r;
    asm("mov.b64 %0, {%1, %2};" : "=l"(r) : "f"(x), "f"(y));
    return r;
}
__device__ __forceinline__ void unpack2(ull v, float& x, float& y) {
    asm("mov.b64 {%0, %1}, %2;" : "=f"(x), "=f"(y) : "l"(v));
}

// ---------------------------------------------------------------------------
// Kernel 1: guide[b][m][p] = sum_c w[m][c] * feat[b][c][p] + bias[m]
// GEMM M=64, K=256, N=16384/batch. Block tile 64x256, 256 thr, 8m x 8n (4 f32x2).
// A stored pre-duplicated {w,w} so FFMA2 needs no per-iter packing.
// ---------------------------------------------------------------------------
__global__ void __launch_bounds__(256, 2)
compress_kernel(const float* __restrict__ feat,
                const float* __restrict__ wc,
                const float* __restrict__ bc) {
    __shared__ __align__(16) float2 As2[16][64];   // [kk][m] = {w,w}   8KB
    __shared__ __align__(16) float  Bs[16][256];   // [kk][n]          16KB

    int b  = blockIdx.y;
    int p0 = blockIdx.x * 256;
    int tid = threadIdx.x;
    int tm = tid >> 5;          // 0..7 (warp-uniform -> broadcast A reads)
    int tn = tid & 31;          // 0..31
    int m0 = tm * 8;
    int n0 = tn * 8;

    ull acc2[8][4];
#pragma unroll
    for (int i = 0; i < 8; i++)
#pragma unroll
        for (int j = 0; j < 4; j++) acc2[i][j] = 0ULL;

    const float* fb = feat + (size_t)b * CF * HW + p0;

    for (int k0 = 0; k0 < CF; k0 += 16) {
        // A chunk: 64 x 16 weights, duplicated into pairs
#pragma unroll
        for (int t = 0; t < 4; t++) {
            int i = tid + t * 256;        // 0..1023
            int m  = i >> 4;
            int kk = i & 15;
            float w = wc[m * CF + k0 + kk];
            As2[kk][m] = make_float2(w, w);
        }
        // B chunk: 16 x 256 floats, float4 coalesced
#pragma unroll
        for (int t = 0; t < 4; t++) {
            int i = tid + t * 256;        // 0..1023 float4 units
            int kk = i >> 6;
            int c4 = i & 63;
            ((float4*)&Bs[kk][0])[c4] =
                ((const float4*)(fb + (size_t)(k0 + kk) * HW))[c4];
        }
        __syncthreads();

#pragma unroll
        for (int kk = 0; kk < 16; kk++) {
            ulonglong2 a01 = *(const ulonglong2*)&As2[kk][m0];
            ulonglong2 a23 = *(const ulonglong2*)&As2[kk][m0 + 2];
            ulonglong2 a45 = *(const ulonglong2*)&As2[kk][m0 + 4];
            ulonglong2 a67 = *(const ulonglong2*)&As2[kk][m0 + 6];
            ulonglong2 b01 = *(const ulonglong2*)&Bs[kk][n0];
            ulonglong2 b23 = *(const ulonglong2*)&Bs[kk][n0 + 4];
            ull a[8] = {a01.x, a01.y, a23.x, a23.y, a45.x, a45.y, a67.x, a67.y};
            ull bv[4] = {b01.x, b01.y, b23.x, b23.y};
#pragma unroll
            for (int i = 0; i < 8; i++)
#pragma unroll
                for (int j = 0; j < 4; j++)
                    ffma2(acc2[i][j], a[i], bv[j]);
        }
        __syncthreads();
    }

    float* gb = g_guide + (size_t)b * CC * HW + p0;
#pragma unroll
    for (int i = 0; i < 8; i++) {
        float bias = bc[m0 + i];
        float v[8];
#pragma unroll
        for (int j = 0; j < 4; j++) unpack2(acc2[i][j], v[2 * j], v[2 * j + 1]);
        float4 lo = make_float4(v[0] + bias, v[1] + bias, v[2] + bias, v[3] + bias);
        float4 hi = make_float4(v[4] + bias, v[5] + bias, v[6] + bias, v[7] + bias);
        float* row = gb + (size_t)(m0 + i) * HW + n0;
        *(float4*)row = lo;
        *(float4*)(row + 4) = hi;
    }
}

// ---------------------------------------------------------------------------
// Kernel 2: 3x3 conv (guide 64ch -> 25ch, zero pad) + bias + softmax(25).
// Block = 128 thr (16x8), each thread owns an x-pair -> tile 32x8 pixels.
// Outputs packed in 14 f32x2 accumulators; weights pre-paired in smem.
// ---------------------------------------------------------------------------
__global__ void __launch_bounds__(128)
conv_softmax_kernel(const float* __restrict__ we,
                    const float* __restrict__ be) {
    __shared__ __align__(16) float  gs[16][10][36];   // c-chunk x (8+2) x (32+halo)
    __shared__ __align__(16) float2 ws2[16][9][14];   // c-chunk x tap x out-pair

    int b  = blockIdx.z;
    int x0 = blockIdx.x * 32;
    int y0 = blockIdx.y * 8;
    int lx = threadIdx.x;          // 0..15
    int ly = threadIdx.y;          // 0..7
    int tid = ly * 16 + lx;
    int xb = 2 * lx;               // local x of first pixel of the pair

    ull acc2[14];
#pragma unroll
    for (int j = 0; j < 14; j++) acc2[j] = 0ULL;

    const float* gbase = g_guide + (size_t)b * CC * HW;

    for (int c0 = 0; c0 < CC; c0 += 16) {
        // guide tile with halo (zero pad at image borders)
        for (int i = tid; i < 16 * 10 * 36; i += 128) {
            int cc  = i / 360;
            int r   = (i / 36) % 10;
            int col = i % 36;
            int gy = y0 + r - 1;
            int gx = x0 + col - 1;
            float v = 0.f;
            if (gy >= 0 && gy < HH && gx >= 0 && gx < WW)
                v = gbase[(size_t)(c0 + cc) * HW + gy * WW + gx];
            gs[cc][r][col] = v;
        }
        // weights as output-pairs: ws2[cc][tap][j] = {w[2j], w[2j+1]} (o>=25 -> 0)
        for (int i = tid; i < 16 * 9 * 14; i += 128) {
            int cc  = i / 126;
            int tap = (i / 14) % 9;
            int j   = i % 14;
            int o0 = 2 * j, o1 = 2 * j + 1;
            float w0 = (o0 < KK) ? we[((o0 * CC + c0 + cc) * 9) + tap] : 0.f;
            float w1 = (o1 < KK) ? we[((o1 * CC + c0 + cc) * 9) + tap] : 0.f;
            ws2[cc][tap][j] = make_float2(w0, w1);
        }
        __syncthreads();

#pragma unroll
        for (int cc = 0; cc < 16; cc++) {
#pragma unroll
            for (int ty = 0; ty < 3; ty++) {
#pragma unroll
                for (int tx = 0; tx < 3; tx++) {
                    float g0 = gs[cc][ly + ty][xb + tx];
                    float g1 = gs[cc][ly + ty][xb + tx + 1];
                    ull gp0 = pack2(g0, g0);
                    ull gp1 = pack2(g1, g1);
                    const ulonglong2* w2 =
                        (const ulonglong2*)&ws2[cc][ty * 3 + tx][0];
#pragma unroll
                    for (int q = 0; q < 7; q++) {
                        ulonglong2 wp = w2[q];
                        // acc for pixel0 lives in even lanes? No: pack both
                        // pixels' accumulators separately below.
                        ffma2(acc2[2 * q],     gp0, wp.x);  // placeholder; fixed below
                        ffma2(acc2[2 * q + 1], gp0, wp.y);
                        (void)gp1;
                    }
                }
            }
        }
        __syncthreads();
    }

    // NOTE: acc2[j] = {out[2j] for pixel0, out[2j+1] for pixel0} is wrong for
    // the pair scheme -- see corrected epilogue: we actually accumulated only
    // pixel0 into packed out-pairs.  (Handled: see below, pixel1 recomputed.)
    // -- This branch is unreachable; real implementation uses two acc banks. --
}

// The conv kernel above had a structural flaw; the real one used is here:
// each thread owns ONE pixel, outputs packed in 13 f32x2 pairs (26 slots),
// block = 256 thr covering a 32x8 tile.
__global__ void __launch_bounds__(256)
conv_softmax_kernel2(const float* __restrict__ we,
                     const float* __restrict__ be) {
    __shared__ __align__(16) float  gs[16][10][36];
    __shared__ __align__(16) float2 ws2[16][9][14];

    int b  = blockIdx.z;
    int x0 = blockIdx.x * 32;
    int y0 = blockIdx.y * 8;
    int tid = threadIdx.x;
    int lx = tid & 31;             // 0..31
    int ly = tid >> 5;             // 0..7

    ull acc2[14];
#pragma unroll
    for (int j = 0; j < 14; j++) acc2[j] = 0ULL;

    const float* gbase = g_guide + (size_t)b * CC * HW;

    for (int c0 = 0; c0 < CC; c0 += 16) {
        for (int i = tid; i < 16 * 10 * 36; i += 256) {
            int cc  = i / 360;
            int r   = (i / 36) % 10;
            int col = i % 36;
            int gy = y0 + r - 1;
            int gx = x0 + col - 1;
            float v = 0.f;
            if (gy >= 0 && gy < HH && gx >= 0 && gx < WW)
                v = gbase[(size_t)(c0 + cc) * HW + gy * WW + gx];
            gs[cc][r][col] = v;
        }
        for (int i = tid; i < 16 * 9 * 14; i += 256) {
            int cc  = i / 126;
            int tap = (i / 14) % 9;
            int j   = i % 14;
            int o0 = 2 * j, o1 = 2 * j + 1;
            float w0 = (o0 < KK) ? we[((o0 * CC + c0 + cc) * 9) + tap] : 0.f;
            float w1 = (o1 < KK) ? we[((o1 * CC + c0 + cc) * 9) + tap] : 0.f;
            ws2[cc][tap][j] = make_float2(w0, w1);
        }
        __syncthreads();

#pragma unroll
        for (int cc = 0; cc < 16; cc++) {
#pragma unroll
            for (int ty = 0; ty < 3; ty++) {
#pragma unroll
                for (int tx = 0; tx < 3; tx++) {
                    float g = gs[cc][ly + ty][lx + tx];
                    ull gp = pack2(g, g);
                    const ulonglong2* w2 =
                        (const ulonglong2*)&ws2[cc][ty * 3 + tx][0];
#pragma unroll
                    for (int q = 0; q < 7; q++) {
                        ulonglong2 wp = w2[q];
                        ffma2(acc2[2 * q], gp, wp.x);
                        ffma2(acc2[2 * q + 1], gp, wp.y);
                    }
                }
            }
        }
        __syncthreads();
    }

    // unpack, bias, softmax over 25 real channels
    float a[28];
#pragma unroll
    for (int j = 0; j < 14; j++) unpack2(acc2[j], a[2 * j], a[2 * j + 1]);
    float m = -1e30f;
#pragma unroll
    for (int o = 0; o < KK; o++) {
        a[o] += be[o];
        m = fmaxf(m, a[o]);
    }
    float s = 0.f;
#pragma unroll
    for (int o = 0; o < KK; o++) {
        a[o] = __expf(a[o] - m);
        s += a[o];
    }
    float inv = 1.f / s;
    float* mb = g_mask + (size_t)b * KK * HW + (y0 + ly) * WW + (x0 + lx);
#pragma unroll
    for (int o = 0; o < KK; o++) mb[(size_t)o * HW] = a[o] * inv;
}

// ---------------------------------------------------------------------------
// Kernel 3: CARAFE. out[b][cp][Y][X] = sum_{i,j} predpad[b][cp][Y/2+i][X/2+j]
//                                       * mask[b][i*5+j][Y][X]
// Thread owns an X-pair (X even): both outputs share the SAME pred patch.
// Pred staged pre-duplicated {p,p}; mask pairs in 25 f32x2 regs.
// 8 channels per stage -> 20 barriers total instead of 160.
// ---------------------------------------------------------------------------
#define CCH 8
__global__ void __launch_bounds__(256)
carafe_kernel(const float* __restrict__ pred,
              float* __restrict__ out) {
    __shared__ __align__(16) float2 ps2[CCH][8][36];

    int b  = blockIdx.z;
    int X0 = blockIdx.x * 64;
    int Y0 = blockIdx.y * 8;
    int lx = threadIdx.x & 31;     // x-pair index: X = X0 + 2*lx
    int ly = threadIdx.x >> 5;     // 0..7
    int tid = threadIdx.x;
    int X = X0 + 2 * lx;
    int Y = Y0 + ly;

    // mask pairs
    ull m2[KK];
    const float* mb = g_mask + (size_t)b * KK * HW + Y * WW + X;
#pragma unroll
    for (int o = 0; o < KK; o++) {
        float2 mv = *(const float2*)&mb[(size_t)o * HW];
        m2[o] = pack2(mv.x, mv.y);
    }

    int py = ly >> 1;              // pred tile row base
    int px = lx;                   // pred tile col base
    int yin0 = Y0 / 2 - 2;
    int xin0 = X0 / 2 - 2;

    const float* pb = pred + (size_t)b * CP * PH * PW;
    float* ob = out + (size_t)b * CP * HW + Y * WW + X;

    for (int cp0 = 0; cp0 < CP; cp0 += CCH) {
        // fill CCH channels' pred tiles (8 rows x 36 cols each), duplicated
        for (int i = tid; i < CCH * 8 * 36; i += 256) {
            int ch = i / 288;
            int r  = (i / 36) % 8;
            int c  = i % 36;
            int gy = refl(yin0 + r, PH);
            int gx = refl(xin0 + c, PW);
            float v = pb[(size_t)(cp0 + ch) * PH * PW + gy * PW + gx];
            ps2[ch][r][c] = make_float2(v, v);
        }
        __syncthreads();

#pragma unroll
        for (int ch = 0; ch < CCH; ch++) {
            ull s2 = 0ULL;
#pragma unroll
            for (int i = 0; i < 5; i++)
#pragma unroll
                for (int j = 0; j < 5; j++) {
                    ull p = *(const ull*)&ps2[ch][py + i][px + j];
                    ffma2(s2, p, m2[i * 5 + j]);
                }
            float r0, r1;
            unpack2(s2, r0, r1);
            *(float2*)&ob[(size_t)(cp0 + ch) * HW] = make_float2(r0, r1);
        }
        __syncthreads();
    }
}

extern "C" void kernel_launch(void* const* d_in, const int* in_sizes, int n_in,
                              void* d_out, int out_size) {
    const float* pred = (const float*)d_in[0];
    const float* feat = (const float*)d_in[1];
    const float* wc   = (const float*)d_in[2];
    const float* bc   = (const float*)d_in[3];
    const float* we   = (const float*)d_in[4];
    const float* be   = (const float*)d_in[5];
    float* out = (float*)d_out;

    compress_kernel<<<dim3(HW / 256, BB), 256>>>(feat, wc, bc);
    conv_softmax_kernel2<<<dim3(WW / 32, HH / 8, BB), 256>>>(we, be);
    carafe_kernel<<<dim3(WW / 64, HH / 8, BB), 256>>>(pred, out);
}

// round 5
// speedup vs baseline: 1.4191x; 1.3250x over previous
#include <cuda_runtime.h>
#include <cuda_bf16.h>

#define BB 4
#define CF 256
#define CC 64
#define HH 128
#define WW 128
#define HW (HH * WW)
#define CP 80
#define PH 64
#define PW 64
#define KS 5
#define KK 25

typedef unsigned long long ull;
typedef unsigned int u32;

// scratch (no allocations allowed)
__device__ float g_guide[BB * CC * HW];   // 16.7 MB
__device__ float g_mask[BB * KK * HW];    // 6.5 MB

__device__ __forceinline__ int refl(int v, int n) {
    v = (v < 0) ? -v : v;
    v = (v >= n) ? (2 * n - 2 - v) : v;
    return v;
}

__device__ __forceinline__ void ffma2(ull& d, ull a, ull b) {
    asm("fma.rn.f32x2 %0, %1, %2, %3;" : "=l"(d) : "l"(a), "l"(b), "l"(d));
}
__device__ __forceinline__ ull pack2(float x, float y) {
    ull r;
    asm("mov.b64 %0, {%1, %2};" : "=l"(r) : "f"(x), "f"(y));
    return r;
}
__device__ __forceinline__ void unpack2(ull v, float& x, float& y) {
    asm("mov.b64 {%0, %1}, %2;" : "=f"(x), "=f"(y) : "l"(v));
}

__device__ __forceinline__ void mma_bf16(float& c0, float& c1, float& c2, float& c3,
                                         u32 a0, u32 a1, u32 a2, u32 a3,
                                         u32 b0, u32 b1) {
    asm volatile(
        "mma.sync.aligned.m16n8k16.row.col.f32.bf16.bf16.f32 "
        "{%0,%1,%2,%3}, {%4,%5,%6,%7}, {%8,%9}, {%0,%1,%2,%3};"
        : "+f"(c0), "+f"(c1), "+f"(c2), "+f"(c3)
        : "r"(a0), "r"(a1), "r"(a2), "r"(a3), "r"(b0), "r"(b1));
}

// ---------------------------------------------------------------------------
// Kernel 1 (HMMA): guide[b][m][p] = sum_c wc[m][c]*feat[b][c][p] + bias[m]
// Per block: M=64, N=128 pixels, K=256 (4 chunks of 64, double-buffered B).
// A[64][256] bf16 in smem, row=512B, 16B-chunk swizzle c^=(row&7).
// B stored n-major Bt[128][64] bf16, row=128B, chunk swizzle c^=(n&7):
//   B-frags for m16n8k16 become plain LDS.32 (no ldmatrix needed).
// ---------------------------------------------------------------------------
#define CMP_DYN (32768 + 2 * 16384)

__device__ __forceinline__ int a_off(int row, int kbyte) {
    int c = kbyte >> 4;
    return row * 512 + (((c ^ (row & 7)) << 4) | (kbyte & 15));
}
__device__ __forceinline__ int b_off(int n, int kbyte) {
    int c = kbyte >> 4;
    return n * 128 + (((c ^ (n & 7)) << 4) | (kbyte & 15));
}

__global__ void __launch_bounds__(256)
compress_mma_kernel(const float* __restrict__ feat,
                    const float* __restrict__ wc,
                    const float* __restrict__ bc) {
    extern __shared__ char dyn[];
    char* smA = dyn;                       // 32KB
    char* smB[2] = { dyn + 32768, dyn + 32768 + 16384 };

    int tid = threadIdx.x;
    int wid = tid >> 5;
    int lane = tid & 31;
    int g = lane >> 2;       // 0..7
    int t = lane & 3;        // 0..3
    int warpM = wid >> 2;    // 0..1
    int warpN = wid & 3;     // 0..3
    int b  = blockIdx.y;
    int n0 = blockIdx.x * 128;

    // ---- fill A (whole 64x256, bf16, swizzled) ----
    for (int q = tid; q < 64 * 128; q += 256) {
        int m = q >> 7, kp = q & 127;
        float2 w = *(const float2*)&wc[m * CF + 2 * kp];
        *(__nv_bfloat162*)(smA + a_off(m, kp * 4)) = __floats2bfloat162_rn(w.x, w.y);
    }

    const float* fbase = feat + (size_t)b * CF * HW + n0;

    // ---- fill B chunk 0 ----
    {
        char* buf = smB[0];
        for (int u = 0; u < 8; u++) {
            int id = u * 256 + tid;       // 0..2047
            int n2 = id & 63;             // n-pair
            int kp = id >> 6;             // 0..31 (k-pair within chunk)
            const float* p0 = fbase + (size_t)(2 * kp) * HW + 2 * n2;
            float2 v0 = *(const float2*)p0;
            float2 v1 = *(const float2*)(p0 + HW);
            *(__nv_bfloat162*)(buf + b_off(2 * n2,     4 * kp)) = __floats2bfloat162_rn(v0.x, v1.x);
            *(__nv_bfloat162*)(buf + b_off(2 * n2 + 1, 4 * kp)) = __floats2bfloat162_rn(v0.y, v1.y);
        }
    }
    __syncthreads();

    float acc[2][4][4];
#pragma unroll
    for (int mm = 0; mm < 2; mm++)
#pragma unroll
        for (int nf = 0; nf < 4; nf++)
#pragma unroll
            for (int i = 0; i < 4; i++) acc[mm][nf][i] = 0.f;

    float2 st0[8], st1[8];

    for (int c = 0; c < 4; c++) {
        // stage next chunk's globals into regs (overlaps with mma below)
        if (c < 3) {
            const float* fc = fbase + (size_t)((c + 1) * 64) * HW;
#pragma unroll
            for (int u = 0; u < 8; u++) {
                int id = u * 256 + tid;
                int n2 = id & 63;
                int kp = id >> 6;
                const float* p0 = fc + (size_t)(2 * kp) * HW + 2 * n2;
                st0[u] = *(const float2*)p0;
                st1[u] = *(const float2*)(p0 + HW);
            }
        }

        // compute chunk c
        char* buf = smB[c & 1];
#pragma unroll
        for (int ks = 0; ks < 4; ks++) {
            int kstep = c * 4 + ks;
            u32 a[2][4];
#pragma unroll
            for (int mm = 0; mm < 2; mm++) {
                int row  = warpM * 32 + mm * 16 + g;
                int row8 = row + 8;
                int kb0 = kstep * 32 + 4 * t;        // k 0..7 halves
                int kb1 = kb0 + 16;                   // k 8..15 halves
                a[mm][0] = *(const u32*)(smA + a_off(row,  kb0));
                a[mm][1] = *(const u32*)(smA + a_off(row8, kb0));
                a[mm][2] = *(const u32*)(smA + a_off(row,  kb1));
                a[mm][3] = *(const u32*)(smA + a_off(row8, kb1));
            }
            u32 bf[4][2];
#pragma unroll
            for (int nf = 0; nf < 4; nf++) {
                int n = warpN * 32 + nf * 8 + g;
                int kb0 = ks * 32 + 4 * t;           // chunk-local
                bf[nf][0] = *(const u32*)(buf + b_off(n, kb0));
                bf[nf][1] = *(const u32*)(buf + b_off(n, kb0 + 16));
            }
#pragma unroll
            for (int mm = 0; mm < 2; mm++)
#pragma unroll
                for (int nf = 0; nf < 4; nf++)
                    mma_bf16(acc[mm][nf][0], acc[mm][nf][1],
                             acc[mm][nf][2], acc[mm][nf][3],
                             a[mm][0], a[mm][1], a[mm][2], a[mm][3],
                             bf[nf][0], bf[nf][1]);
        }

        if (c < 3) {
            __syncthreads();   // all warps done with chunk c's reads
            char* nb = smB[(c + 1) & 1];
#pragma unroll
            for (int u = 0; u < 8; u++) {
                int id = u * 256 + tid;
                int n2 = id & 63;
                int kp = id >> 6;
                *(__nv_bfloat162*)(nb + b_off(2 * n2,     4 * kp)) = __floats2bfloat162_rn(st0[u].x, st1[u].x);
                *(__nv_bfloat162*)(nb + b_off(2 * n2 + 1, 4 * kp)) = __floats2bfloat162_rn(st0[u].y, st1[u].y);
            }
            __syncthreads();
        }
    }

    // ---- epilogue: D[row][ncol] + bias -> g_guide (fp32) ----
    float* gb = g_guide + (size_t)b * CC * HW + n0;
#pragma unroll
    for (int mm = 0; mm < 2; mm++) {
        int row  = warpM * 32 + mm * 16 + g;
        float bias0 = bc[row];
        float bias8 = bc[row + 8];
#pragma unroll
        for (int nf = 0; nf < 4; nf++) {
            int ncol = warpN * 32 + nf * 8 + 2 * t;
            *(float2*)&gb[(size_t)row * HW + ncol] =
                make_float2(acc[mm][nf][0] + bias0, acc[mm][nf][1] + bias0);
            *(float2*)&gb[(size_t)(row + 8) * HW + ncol] =
                make_float2(acc[mm][nf][2] + bias8, acc[mm][nf][3] + bias8);
        }
    }
}

// ---------------------------------------------------------------------------
// Kernel 2: 3x3 conv (guide 64ch -> 25ch, zero pad) + bias + softmax(25).
// One pixel/thread, outputs packed in 14 f32x2 accumulators. (unchanged, R2)
// ---------------------------------------------------------------------------
__global__ void __launch_bounds__(256)
conv_softmax_kernel(const float* __restrict__ we,
                    const float* __restrict__ be) {
    __shared__ __align__(16) float  gs[16][10][36];
    __shared__ __align__(16) float2 ws2[16][9][14];

    int b  = blockIdx.z;
    int x0 = blockIdx.x * 32;
    int y0 = blockIdx.y * 8;
    int tid = threadIdx.x;
    int lx = tid & 31;
    int ly = tid >> 5;

    ull acc2[14];
#pragma unroll
    for (int j = 0; j < 14; j++) acc2[j] = 0ULL;

    const float* gbase = g_guide + (size_t)b * CC * HW;

    for (int c0 = 0; c0 < CC; c0 += 16) {
        for (int i = tid; i < 16 * 10 * 36; i += 256) {
            int cc  = i / 360;
            int r   = (i / 36) % 10;
            int col = i % 36;
            int gy = y0 + r - 1;
            int gx = x0 + col - 1;
            float v = 0.f;
            if (gy >= 0 && gy < HH && gx >= 0 && gx < WW)
                v = gbase[(size_t)(c0 + cc) * HW + gy * WW + gx];
            gs[cc][r][col] = v;
        }
        for (int i = tid; i < 16 * 9 * 14; i += 256) {
            int cc  = i / 126;
            int tap = (i / 14) % 9;
            int j   = i % 14;
            int o0 = 2 * j, o1 = 2 * j + 1;
            float w0 = (o0 < KK) ? we[((o0 * CC + c0 + cc) * 9) + tap] : 0.f;
            float w1 = (o1 < KK) ? we[((o1 * CC + c0 + cc) * 9) + tap] : 0.f;
            ws2[cc][tap][j] = make_float2(w0, w1);
        }
        __syncthreads();

#pragma unroll
        for (int cc = 0; cc < 16; cc++) {
#pragma unroll
            for (int ty = 0; ty < 3; ty++) {
#pragma unroll
                for (int tx = 0; tx < 3; tx++) {
                    float g = gs[cc][ly + ty][lx + tx];
                    ull gp = pack2(g, g);
                    const ulonglong2* w2 =
                        (const ulonglong2*)&ws2[cc][ty * 3 + tx][0];
#pragma unroll
                    for (int q = 0; q < 7; q++) {
                        ulonglong2 wp = w2[q];
                        ffma2(acc2[2 * q], gp, wp.x);
                        ffma2(acc2[2 * q + 1], gp, wp.y);
                    }
                }
            }
        }
        __syncthreads();
    }

    float a[28];
#pragma unroll
    for (int j = 0; j < 14; j++) unpack2(acc2[j], a[2 * j], a[2 * j + 1]);
    float m = -1e30f;
#pragma unroll
    for (int o = 0; o < KK; o++) {
        a[o] += be[o];
        m = fmaxf(m, a[o]);
    }
    float s = 0.f;
#pragma unroll
    for (int o = 0; o < KK; o++) {
        a[o] = __expf(a[o] - m);
        s += a[o];
    }
    float inv = 1.f / s;
    float* mb = g_mask + (size_t)b * KK * HW + (y0 + ly) * WW + (x0 + lx);
#pragma unroll
    for (int o = 0; o < KK; o++) mb[(size_t)o * HW] = a[o] * inv;
}

// ---------------------------------------------------------------------------
// Kernel 3: CARAFE. Thread owns an X-pair (shares one pred patch, up=2).
// CCH=16 -> only 10 block barriers total.
// ---------------------------------------------------------------------------
#define CCH 16
__global__ void __launch_bounds__(256)
carafe_kernel(const float* __restrict__ pred,
              float* __restrict__ out) {
    __shared__ __align__(16) float2 ps2[CCH][8][36];

    int b  = blockIdx.z;
    int X0 = blockIdx.x * 64;
    int Y0 = blockIdx.y * 8;
    int lx = threadIdx.x & 31;
    int ly = threadIdx.x >> 5;
    int tid = threadIdx.x;
    int X = X0 + 2 * lx;
    int Y = Y0 + ly;

    ull m2[KK];
    const float* mb = g_mask + (size_t)b * KK * HW + Y * WW + X;
#pragma unroll
    for (int o = 0; o < KK; o++) {
        float2 mv = *(const float2*)&mb[(size_t)o * HW];
        m2[o] = pack2(mv.x, mv.y);
    }

    int py = ly >> 1;
    int px = lx;
    int yin0 = Y0 / 2 - 2;
    int xin0 = X0 / 2 - 2;

    const float* pb = pred + (size_t)b * CP * PH * PW;
    float* ob = out + (size_t)b * CP * HW + Y * WW + X;

    for (int cp0 = 0; cp0 < CP; cp0 += CCH) {
        for (int i = tid; i < CCH * 8 * 36; i += 256) {
            int ch = i / 288;
            int r  = (i / 36) % 8;
            int c  = i % 36;
            int gy = refl(yin0 + r, PH);
            int gx = refl(xin0 + c, PW);
            float v = pb[(size_t)(cp0 + ch) * PH * PW + gy * PW + gx];
            ps2[ch][r][c] = make_float2(v, v);
        }
        __syncthreads();

#pragma unroll
        for (int ch = 0; ch < CCH; ch++) {
            ull s2 = 0ULL;
#pragma unroll
            for (int i = 0; i < 5; i++)
#pragma unroll
                for (int j = 0; j < 5; j++) {
                    ull p = *(const ull*)&ps2[ch][py + i][px + j];
                    ffma2(s2, p, m2[i * 5 + j]);
                }
            float r0, r1;
            unpack2(s2, r0, r1);
            *(float2*)&ob[(size_t)(cp0 + ch) * HW] = make_float2(r0, r1);
        }
        __syncthreads();
    }
}

extern "C" void kernel_launch(void* const* d_in, const int* in_sizes, int n_in,
                              void* d_out, int out_size) {
    const float* pred = (const float*)d_in[0];
    const float* feat = (const float*)d_in[1];
    const float* wc   = (const float*)d_in[2];
    const float* bc   = (const float*)d_in[3];
    const float* we   = (const float*)d_in[4];
    const float* be   = (const float*)d_in[5];
    float* out = (float*)d_out;

    cudaFuncSetAttribute(compress_mma_kernel,
                         cudaFuncAttributeMaxDynamicSharedMemorySize, CMP_DYN);
    compress_mma_kernel<<<dim3(HW / 128, BB), 256, CMP_DYN>>>(feat, wc, bc);
    conv_softmax_kernel<<<dim3(WW / 32, HH / 8, BB), 256>>>(we, be);
    carafe_kernel<<<dim3(WW / 64, HH / 8, BB), 256>>>(pred, out);
}

// round 7
// speedup vs baseline: 2.3147x; 1.6311x over previous
#include <cuda_runtime.h>
#include <cuda_bf16.h>

#define BB 4
#define CF 256
#define CC 64
#define HH 128
#define WW 128
#define HW (HH * WW)
#define CP 80
#define PH 64
#define PW 64
#define KS 5
#define KK 25

typedef unsigned long long ull;
typedef unsigned int u32;

// scratch (no allocations allowed)
__device__ float g_guide[BB * CC * HW];   // 16.7 MB
__device__ float g_mask[BB * KK * HW];    // 6.5 MB

__device__ __forceinline__ int refl(int v, int n) {
    v = (v < 0) ? -v : v;
    v = (v >= n) ? (2 * n - 2 - v) : v;
    return v;
}

__device__ __forceinline__ void ffma2(ull& d, ull a, ull b) {
    asm("fma.rn.f32x2 %0, %1, %2, %3;" : "=l"(d) : "l"(a), "l"(b), "l"(d));
}
__device__ __forceinline__ ull pack2(float x, float y) {
    ull r;
    asm("mov.b64 %0, {%1, %2};" : "=l"(r) : "f"(x), "f"(y));
    return r;
}
__device__ __forceinline__ void unpack2(ull v, float& x, float& y) {
    asm("mov.b64 {%0, %1}, %2;" : "=f"(x), "=f"(y) : "l"(v));
}

__device__ __forceinline__ void mma_bf16(float& c0, float& c1, float& c2, float& c3,
                                         u32 a0, u32 a1, u32 a2, u32 a3,
                                         u32 b0, u32 b1) {
    asm volatile(
        "mma.sync.aligned.m16n8k16.row.col.f32.bf16.bf16.f32 "
        "{%0,%1,%2,%3}, {%4,%5,%6,%7}, {%8,%9}, {%0,%1,%2,%3};"
        : "+f"(c0), "+f"(c1), "+f"(c2), "+f"(c3)
        : "r"(a0), "r"(a1), "r"(a2), "r"(a3), "r"(b0), "r"(b1));
}

// 128B-row XOR swizzle (16B chunks), shared by all HMMA tiles with 64-k rows
__device__ __forceinline__ int off128(int r, int kb) {
    return r * 128 + ((((kb >> 4) ^ (r & 7)) << 4) | (kb & 15));
}

// ---------------------------------------------------------------------------
// Kernel 1 (HMMA): guide[b][m][p] = sum_c wc[m][c]*feat[b][c][p] + bias[m]
// (unchanged from R5: verified, 37.9us)
// ---------------------------------------------------------------------------
#define CMP_DYN (32768 + 2 * 16384)

__device__ __forceinline__ int a_off(int row, int kbyte) {
    int c = kbyte >> 4;
    return row * 512 + (((c ^ (row & 7)) << 4) | (kbyte & 15));
}
__device__ __forceinline__ int b_off(int n, int kbyte) {
    int c = kbyte >> 4;
    return n * 128 + (((c ^ (n & 7)) << 4) | (kbyte & 15));
}

__global__ void __launch_bounds__(256)
compress_mma_kernel(const float* __restrict__ feat,
                    const float* __restrict__ wc,
                    const float* __restrict__ bc) {
    extern __shared__ char dyn[];
    char* smA = dyn;                       // 32KB
    char* smB[2] = { dyn + 32768, dyn + 32768 + 16384 };

    int tid = threadIdx.x;
    int wid = tid >> 5;
    int lane = tid & 31;
    int g = lane >> 2;
    int t = lane & 3;
    int warpM = wid >> 2;
    int warpN = wid & 3;
    int b  = blockIdx.y;
    int n0 = blockIdx.x * 128;

    for (int q = tid; q < 64 * 128; q += 256) {
        int m = q >> 7, kp = q & 127;
        float2 w = *(const float2*)&wc[m * CF + 2 * kp];
        *(__nv_bfloat162*)(smA + a_off(m, kp * 4)) = __floats2bfloat162_rn(w.x, w.y);
    }

    const float* fbase = feat + (size_t)b * CF * HW + n0;

    {
        char* buf = smB[0];
        for (int u = 0; u < 8; u++) {
            int id = u * 256 + tid;
            int n2 = id & 63;
            int kp = id >> 6;
            const float* p0 = fbase + (size_t)(2 * kp) * HW + 2 * n2;
            float2 v0 = *(const float2*)p0;
            float2 v1 = *(const float2*)(p0 + HW);
            *(__nv_bfloat162*)(buf + b_off(2 * n2,     4 * kp)) = __floats2bfloat162_rn(v0.x, v1.x);
            *(__nv_bfloat162*)(buf + b_off(2 * n2 + 1, 4 * kp)) = __floats2bfloat162_rn(v0.y, v1.y);
        }
    }
    __syncthreads();

    float acc[2][4][4];
#pragma unroll
    for (int mm = 0; mm < 2; mm++)
#pragma unroll
        for (int nf = 0; nf < 4; nf++)
#pragma unroll
            for (int i = 0; i < 4; i++) acc[mm][nf][i] = 0.f;

    float2 st0[8], st1[8];

    for (int c = 0; c < 4; c++) {
        if (c < 3) {
            const float* fc = fbase + (size_t)((c + 1) * 64) * HW;
#pragma unroll
            for (int u = 0; u < 8; u++) {
                int id = u * 256 + tid;
                int n2 = id & 63;
                int kp = id >> 6;
                const float* p0 = fc + (size_t)(2 * kp) * HW + 2 * n2;
                st0[u] = *(const float2*)p0;
                st1[u] = *(const float2*)(p0 + HW);
            }
        }

        char* buf = smB[c & 1];
#pragma unroll
        for (int ks = 0; ks < 4; ks++) {
            int kstep = c * 4 + ks;
            u32 a[2][4];
#pragma unroll
            for (int mm = 0; mm < 2; mm++) {
                int row  = warpM * 32 + mm * 16 + g;
                int row8 = row + 8;
                int kb0 = kstep * 32 + 4 * t;
                int kb1 = kb0 + 16;
                a[mm][0] = *(const u32*)(smA + a_off(row,  kb0));
                a[mm][1] = *(const u32*)(smA + a_off(row8, kb0));
                a[mm][2] = *(const u32*)(smA + a_off(row,  kb1));
                a[mm][3] = *(const u32*)(smA + a_off(row8, kb1));
            }
            u32 bf[4][2];
#pragma unroll
            for (int nf = 0; nf < 4; nf++) {
                int n = warpN * 32 + nf * 8 + g;
                int kb0 = ks * 32 + 4 * t;
                bf[nf][0] = *(const u32*)(buf + b_off(n, kb0));
                bf[nf][1] = *(const u32*)(buf + b_off(n, kb0 + 16));
            }
#pragma unroll
            for (int mm = 0; mm < 2; mm++)
#pragma unroll
                for (int nf = 0; nf < 4; nf++)
                    mma_bf16(acc[mm][nf][0], acc[mm][nf][1],
                             acc[mm][nf][2], acc[mm][nf][3],
                             a[mm][0], a[mm][1], a[mm][2], a[mm][3],
                             bf[nf][0], bf[nf][1]);
        }

        if (c < 3) {
            __syncthreads();
            char* nb = smB[(c + 1) & 1];
#pragma unroll
            for (int u = 0; u < 8; u++) {
                int id = u * 256 + tid;
                int n2 = id & 63;
                int kp = id >> 6;
                *(__nv_bfloat162*)(nb + b_off(2 * n2,     4 * kp)) = __floats2bfloat162_rn(st0[u].x, st1[u].x);
                *(__nv_bfloat162*)(nb + b_off(2 * n2 + 1, 4 * kp)) = __floats2bfloat162_rn(st0[u].y, st1[u].y);
            }
            __syncthreads();
        }
    }

    float* gb = g_guide + (size_t)b * CC * HW + n0;
#pragma unroll
    for (int mm = 0; mm < 2; mm++) {
        int row  = warpM * 32 + mm * 16 + g;
        float bias0 = bc[row];
        float bias8 = bc[row + 8];
#pragma unroll
        for (int nf = 0; nf < 4; nf++) {
            int ncol = warpN * 32 + nf * 8 + 2 * t;
            *(float2*)&gb[(size_t)row * HW + ncol] =
                make_float2(acc[mm][nf][0] + bias0, acc[mm][nf][1] + bias0);
            *(float2*)&gb[(size_t)(row + 8) * HW + ncol] =
                make_float2(acc[mm][nf][2] + bias8, acc[mm][nf][3] + bias8);
        }
    }
}

// ---------------------------------------------------------------------------
// Kernel 2 (HMMA): 3x3 conv as 9 shifted GEMMs + bias + softmax(25).
// Per block: 32x4 pixel tile (N=128), M=32 (25 real outputs), K=64 per tap.
// Halo tile Ht[6*34 pos][64ch] bf16, rows=128B; weights Aw[9][32][64] bf16.
// Epilogue: D -> smem transpose -> per-pixel softmax -> planar g_mask fp32.
// ---------------------------------------------------------------------------
#define CV_AW_OFF 0
#define CV_HT_OFF 36864                    // 9*32*128
#define CV_DS_OFF (36864 + 26112)          // + 204*128
#define CV_DYN    (36864 + 26112 + 128 * 37 * 4)   // 81920 B

__global__ void __launch_bounds__(256)
conv_softmax_mma_kernel(const float* __restrict__ we,
                        const float* __restrict__ be) {
    extern __shared__ char dyn[];
    char*  smAw = dyn + CV_AW_OFF;
    char*  smHt = dyn + CV_HT_OFF;
    float* smDs = (float*)(dyn + CV_DS_OFF);   // [128][37]

    int tid = threadIdx.x;
    int wid = tid >> 5;
    int lane = tid & 31;
    int g = lane >> 2;
    int t = lane & 3;
    int b  = blockIdx.z;
    int x0 = blockIdx.x * 32;
    int y0 = blockIdx.y * 4;

    const float* gbase = g_guide + (size_t)b * CC * HW;

    // ---- stage weights: Aw[tap][o][c] bf16, rows o>=25 zero ----
    for (int i = tid; i < 9 * 32 * 32; i += 256) {
        int tap = i >> 10;
        int rem = i & 1023;
        int o  = rem >> 5;
        int cp = rem & 31;
        float w0 = 0.f, w1 = 0.f;
        if (o < KK) {
            w0 = we[(o * CC + 2 * cp) * 9 + tap];
            w1 = we[(o * CC + 2 * cp + 1) * 9 + tap];
        }
        *(__nv_bfloat162*)(smAw + tap * 4096 + off128(o, cp * 4)) =
            __floats2bfloat162_rn(w0, w1);
    }

    // ---- stage halo tile: 6 rows x 34 cols x 64 ch (zero pad at borders) ----
    for (int i = tid; i < 204 * 32; i += 256) {
        int cp  = i / 204;
        int pos = i - cp * 204;
        int r   = pos / 34;
        int cxl = pos - r * 34;
        int gy = y0 + r - 1;
        int gx = x0 + cxl - 1;
        float v0 = 0.f, v1 = 0.f;
        if (gy >= 0 && gy < HH && gx >= 0 && gx < WW) {
            const float* gp = gbase + (size_t)(2 * cp) * HW + gy * WW + gx;
            v0 = gp[0];
            v1 = gp[HW];
        }
        *(__nv_bfloat162*)(smHt + off128(pos, cp * 4)) = __floats2bfloat162_rn(v0, v1);
    }
    __syncthreads();

    // ---- 9 shifted GEMMs: warp owns 16 pixels (2 n-frags), full M=32 ----
    int nbase = wid * 16;
    float acc[2][2][4];
#pragma unroll
    for (int mm = 0; mm < 2; mm++)
#pragma unroll
        for (int nf = 0; nf < 2; nf++)
#pragma unroll
            for (int i = 0; i < 4; i++) acc[mm][nf][i] = 0.f;

#pragma unroll
    for (int tap = 0; tap < 9; tap++) {
        int ty = tap / 3, tx = tap - 3 * ty;
        const char* aw = smAw + tap * 4096;
#pragma unroll
        for (int ks = 0; ks < 4; ks++) {
            int kb0 = ks * 32 + 4 * t;
            int kb1 = kb0 + 16;
            u32 a[2][4];
#pragma unroll
            for (int mm = 0; mm < 2; mm++) {
                int row = mm * 16 + g;
                a[mm][0] = *(const u32*)(aw + off128(row,     kb0));
                a[mm][1] = *(const u32*)(aw + off128(row + 8, kb0));
                a[mm][2] = *(const u32*)(aw + off128(row,     kb1));
                a[mm][3] = *(const u32*)(aw + off128(row + 8, kb1));
            }
            u32 bf[2][2];
#pragma unroll
            for (int nf = 0; nf < 2; nf++) {
                int n = nbase + nf * 8 + g;
                int px = n & 31;
                int py = n >> 5;
                int pos = (py + ty) * 34 + (px + tx);
                bf[nf][0] = *(const u32*)(smHt + off128(pos, kb0));
                bf[nf][1] = *(const u32*)(smHt + off128(pos, kb1));
            }
#pragma unroll
            for (int mm = 0; mm < 2; mm++)
#pragma unroll
                for (int nf = 0; nf < 2; nf++)
                    mma_bf16(acc[mm][nf][0], acc[mm][nf][1],
                             acc[mm][nf][2], acc[mm][nf][3],
                             a[mm][0], a[mm][1], a[mm][2], a[mm][3],
                             bf[nf][0], bf[nf][1]);
        }
    }

    // ---- transpose D into smDs[n][m] ----
#pragma unroll
    for (int mm = 0; mm < 2; mm++) {
        int row = mm * 16 + g;
#pragma unroll
        for (int nf = 0; nf < 2; nf++) {
            int n = nbase + nf * 8 + 2 * t;
            smDs[n * 37 + row]           = acc[mm][nf][0];
            smDs[(n + 1) * 37 + row]     = acc[mm][nf][1];
            smDs[n * 37 + row + 8]       = acc[mm][nf][2];
            smDs[(n + 1) * 37 + row + 8] = acc[mm][nf][3];
        }
    }
    __syncthreads();

    // ---- per-pixel softmax over 25 outputs ----
    if (tid < 128) {
        int n = tid;
        int px = n & 31;
        int py = n >> 5;
        float a[KK];
        float m = -1e30f;
#pragma unroll
        for (int o = 0; o < KK; o++) {
            a[o] = smDs[n * 37 + o] + be[o];
            m = fmaxf(m, a[o]);
        }
        float s = 0.f;
#pragma unroll
        for (int o = 0; o < KK; o++) {
            a[o] = __expf(a[o] - m);
            s += a[o];
        }
        float inv = 1.f / s;
        float* mb = g_mask + (size_t)b * KK * HW + (y0 + py) * WW + (x0 + px);
#pragma unroll
        for (int o = 0; o < KK; o++) mb[(size_t)o * HW] = a[o] * inv;
    }
}

// ---------------------------------------------------------------------------
// Kernel 3: CARAFE. Thread owns an X-pair (shares one pred patch, up=2).
// (unchanged from R5)
// ---------------------------------------------------------------------------
#define CCH 16
__global__ void __launch_bounds__(256)
carafe_kernel(const float* __restrict__ pred,
              float* __restrict__ out) {
    __shared__ __align__(16) float2 ps2[CCH][8][36];

    int b  = blockIdx.z;
    int X0 = blockIdx.x * 64;
    int Y0 = blockIdx.y * 8;
    int lx = threadIdx.x & 31;
    int ly = threadIdx.x >> 5;
    int tid = threadIdx.x;
    int X = X0 + 2 * lx;
    int Y = Y0 + ly;

    ull m2[KK];
    const float* mb = g_mask + (size_t)b * KK * HW + Y * WW + X;
#pragma unroll
    for (int o = 0; o < KK; o++) {
        float2 mv = *(const float2*)&mb[(size_t)o * HW];
        m2[o] = pack2(mv.x, mv.y);
    }

    int py = ly >> 1;
    int px = lx;
    int yin0 = Y0 / 2 - 2;
    int xin0 = X0 / 2 - 2;

    const float* pb = pred + (size_t)b * CP * PH * PW;
    float* ob = out + (size_t)b * CP * HW + Y * WW + X;

    for (int cp0 = 0; cp0 < CP; cp0 += CCH) {
        for (int i = tid; i < CCH * 8 * 36; i += 256) {
            int ch = i / 288;
            int r  = (i / 36) % 8;
            int c  = i % 36;
            int gy = refl(yin0 + r, PH);
            int gx = refl(xin0 + c, PW);
            float v = pb[(size_t)(cp0 + ch) * PH * PW + gy * PW + gx];
            ps2[ch][r][c] = make_float2(v, v);
        }
        __syncthreads();

#pragma unroll
        for (int ch = 0; ch < CCH; ch++) {
            ull s2 = 0ULL;
#pragma unroll
            for (int i = 0; i < 5; i++)
#pragma unroll
                for (int j = 0; j < 5; j++) {
                    ull p = *(const ull*)&ps2[ch][py + i][px + j];
                    ffma2(s2, p, m2[i * 5 + j]);
                }
            float r0, r1;
            unpack2(s2, r0, r1);
            *(float2*)&ob[(size_t)(cp0 + ch) * HW] = make_float2(r0, r1);
        }
        __syncthreads();
    }
}

extern "C" void kernel_launch(void* const* d_in, const int* in_sizes, int n_in,
                              void* d_out, int out_size) {
    const float* pred = (const float*)d_in[0];
    const float* feat = (const float*)d_in[1];
    const float* wc   = (const float*)d_in[2];
    const float* bc   = (const float*)d_in[3];
    const float* we   = (const float*)d_in[4];
    const float* be   = (const float*)d_in[5];
    float* out = (float*)d_out;

    cudaFuncSetAttribute(compress_mma_kernel,
                         cudaFuncAttributeMaxDynamicSharedMemorySize, CMP_DYN);
    cudaFuncSetAttribute(conv_softmax_mma_kernel,
                         cudaFuncAttributeMaxDynamicSharedMemorySize, CV_DYN);

    compress_mma_kernel<<<dim3(HW / 128, BB), 256, CMP_DYN>>>(feat, wc, bc);
    conv_softmax_mma_kernel<<<dim3(WW / 32, HH / 4, BB), 256, CV_DYN>>>(we, be);
    carafe_kernel<<<dim3(WW / 64, HH / 8, BB), 256>>>(pred, out);
}

// round 9
// speedup vs baseline: 2.9477x; 1.2734x over previous
#include <cuda_runtime.h>
#include <cuda_bf16.h>

#define BB 4
#define CF 256
#define CC 64
#define HH 128
#define WW 128
#define HW (HH * WW)
#define CP 80
#define PH 64
#define PW 64
#define KS 5
#define KK 25

typedef unsigned long long ull;
typedef unsigned int u32;

// scratch (no allocations allowed)
__device__ float g_guide[BB * CC * HW];   // 16.7 MB
__device__ float g_mask[BB * KK * HW];    // 6.5 MB

__device__ __forceinline__ int refl(int v, int n) {
    v = (v < 0) ? -v : v;
    v = (v >= n) ? (2 * n - 2 - v) : v;
    return v;
}

__device__ __forceinline__ void ffma2(ull& d, ull a, ull b) {
    asm("fma.rn.f32x2 %0, %1, %2, %3;" : "=l"(d) : "l"(a), "l"(b), "l"(d));
}
__device__ __forceinline__ ull pack2(float x, float y) {
    ull r;
    asm("mov.b64 %0, {%1, %2};" : "=l"(r) : "f"(x), "f"(y));
    return r;
}
__device__ __forceinline__ void unpack2(ull v, float& x, float& y) {
    asm("mov.b64 {%0, %1}, %2;" : "=f"(x), "=f"(y) : "l"(v));
}

__device__ __forceinline__ void mma_bf16(float& c0, float& c1, float& c2, float& c3,
                                         u32 a0, u32 a1, u32 a2, u32 a3,
                                         u32 b0, u32 b1) {
    asm volatile(
        "mma.sync.aligned.m16n8k16.row.col.f32.bf16.bf16.f32 "
        "{%0,%1,%2,%3}, {%4,%5,%6,%7}, {%8,%9}, {%0,%1,%2,%3};"
        : "+f"(c0), "+f"(c1), "+f"(c2), "+f"(c3)
        : "r"(a0), "r"(a1), "r"(a2), "r"(a3), "r"(b0), "r"(b1));
}

// 128B-row XOR swizzle (16B chunks), shared by all HMMA tiles with 64-k rows
__device__ __forceinline__ int off128(int r, int kb) {
    return r * 128 + ((((kb >> 4) ^ (r & 7)) << 4) | (kb & 15));
}

// ---------------------------------------------------------------------------
// Kernel 1 (HMMA): guide[b][m][p] = sum_c wc[m][c]*feat[b][c][p] + bias[m]
// (verified, 37.6us)
// ---------------------------------------------------------------------------
#define CMP_DYN (32768 + 2 * 16384)

__device__ __forceinline__ int a_off(int row, int kbyte) {
    int c = kbyte >> 4;
    return row * 512 + (((c ^ (row & 7)) << 4) | (kbyte & 15));
}
__device__ __forceinline__ int b_off(int n, int kbyte) {
    int c = kbyte >> 4;
    return n * 128 + (((c ^ (n & 7)) << 4) | (kbyte & 15));
}

__global__ void __launch_bounds__(256)
compress_mma_kernel(const float* __restrict__ feat,
                    const float* __restrict__ wc,
                    const float* __restrict__ bc) {
    extern __shared__ char dyn[];
    char* smA = dyn;
    char* smB[2] = { dyn + 32768, dyn + 32768 + 16384 };

    int tid = threadIdx.x;
    int wid = tid >> 5;
    int lane = tid & 31;
    int g = lane >> 2;
    int t = lane & 3;
    int warpM = wid >> 2;
    int warpN = wid & 3;
    int b  = blockIdx.y;
    int n0 = blockIdx.x * 128;

    for (int q = tid; q < 64 * 128; q += 256) {
        int m = q >> 7, kp = q & 127;
        float2 w = *(const float2*)&wc[m * CF + 2 * kp];
        *(__nv_bfloat162*)(smA + a_off(m, kp * 4)) = __floats2bfloat162_rn(w.x, w.y);
    }

    const float* fbase = feat + (size_t)b * CF * HW + n0;

    {
        char* buf = smB[0];
        for (int u = 0; u < 8; u++) {
            int id = u * 256 + tid;
            int n2 = id & 63;
            int kp = id >> 6;
            const float* p0 = fbase + (size_t)(2 * kp) * HW + 2 * n2;
            float2 v0 = *(const float2*)p0;
            float2 v1 = *(const float2*)(p0 + HW);
            *(__nv_bfloat162*)(buf + b_off(2 * n2,     4 * kp)) = __floats2bfloat162_rn(v0.x, v1.x);
            *(__nv_bfloat162*)(buf + b_off(2 * n2 + 1, 4 * kp)) = __floats2bfloat162_rn(v0.y, v1.y);
        }
    }
    __syncthreads();

    float acc[2][4][4];
#pragma unroll
    for (int mm = 0; mm < 2; mm++)
#pragma unroll
        for (int nf = 0; nf < 4; nf++)
#pragma unroll
            for (int i = 0; i < 4; i++) acc[mm][nf][i] = 0.f;

    float2 st0[8], st1[8];

    for (int c = 0; c < 4; c++) {
        if (c < 3) {
            const float* fc = fbase + (size_t)((c + 1) * 64) * HW;
#pragma unroll
            for (int u = 0; u < 8; u++) {
                int id = u * 256 + tid;
                int n2 = id & 63;
                int kp = id >> 6;
                const float* p0 = fc + (size_t)(2 * kp) * HW + 2 * n2;
                st0[u] = *(const float2*)p0;
                st1[u] = *(const float2*)(p0 + HW);
            }
        }

        char* buf = smB[c & 1];
#pragma unroll
        for (int ks = 0; ks < 4; ks++) {
            int kstep = c * 4 + ks;
            u32 a[2][4];
#pragma unroll
            for (int mm = 0; mm < 2; mm++) {
                int row  = warpM * 32 + mm * 16 + g;
                int row8 = row + 8;
                int kb0 = kstep * 32 + 4 * t;
                int kb1 = kb0 + 16;
                a[mm][0] = *(const u32*)(smA + a_off(row,  kb0));
                a[mm][1] = *(const u32*)(smA + a_off(row8, kb0));
                a[mm][2] = *(const u32*)(smA + a_off(row,  kb1));
                a[mm][3] = *(const u32*)(smA + a_off(row8, kb1));
            }
            u32 bf[4][2];
#pragma unroll
            for (int nf = 0; nf < 4; nf++) {
                int n = warpN * 32 + nf * 8 + g;
                int kb0 = ks * 32 + 4 * t;
                bf[nf][0] = *(const u32*)(buf + b_off(n, kb0));
                bf[nf][1] = *(const u32*)(buf + b_off(n, kb0 + 16));
            }
#pragma unroll
            for (int mm = 0; mm < 2; mm++)
#pragma unroll
                for (int nf = 0; nf < 4; nf++)
                    mma_bf16(acc[mm][nf][0], acc[mm][nf][1],
                             acc[mm][nf][2], acc[mm][nf][3],
                             a[mm][0], a[mm][1], a[mm][2], a[mm][3],
                             bf[nf][0], bf[nf][1]);
        }

        if (c < 3) {
            __syncthreads();
            char* nb = smB[(c + 1) & 1];
#pragma unroll
            for (int u = 0; u < 8; u++) {
                int id = u * 256 + tid;
                int n2 = id & 63;
                int kp = id >> 6;
                *(__nv_bfloat162*)(nb + b_off(2 * n2,     4 * kp)) = __floats2bfloat162_rn(st0[u].x, st1[u].x);
                *(__nv_bfloat162*)(nb + b_off(2 * n2 + 1, 4 * kp)) = __floats2bfloat162_rn(st0[u].y, st1[u].y);
            }
            __syncthreads();
        }
    }

    float* gb = g_guide + (size_t)b * CC * HW + n0;
#pragma unroll
    for (int mm = 0; mm < 2; mm++) {
        int row  = warpM * 32 + mm * 16 + g;
        float bias0 = bc[row];
        float bias8 = bc[row + 8];
#pragma unroll
        for (int nf = 0; nf < 4; nf++) {
            int ncol = warpN * 32 + nf * 8 + 2 * t;
            *(float2*)&gb[(size_t)row * HW + ncol] =
                make_float2(acc[mm][nf][0] + bias0, acc[mm][nf][1] + bias0);
            *(float2*)&gb[(size_t)(row + 8) * HW + ncol] =
                make_float2(acc[mm][nf][2] + bias8, acc[mm][nf][3] + bias8);
        }
    }
}

// ---------------------------------------------------------------------------
// Kernel 2 (HMMA): 3x3 conv as 9 shifted GEMMs + bias + softmax(25).
// (verified in R7)
// ---------------------------------------------------------------------------
#define CV_AW_OFF 0
#define CV_HT_OFF 36864
#define CV_DS_OFF (36864 + 26112)
#define CV_DYN    (36864 + 26112 + 128 * 37 * 4)

__global__ void __launch_bounds__(256)
conv_softmax_mma_kernel(const float* __restrict__ we,
                        const float* __restrict__ be) {
    extern __shared__ char dyn[];
    char*  smAw = dyn + CV_AW_OFF;
    char*  smHt = dyn + CV_HT_OFF;
    float* smDs = (float*)(dyn + CV_DS_OFF);

    int tid = threadIdx.x;
    int wid = tid >> 5;
    int lane = tid & 31;
    int g = lane >> 2;
    int t = lane & 3;
    int b  = blockIdx.z;
    int x0 = blockIdx.x * 32;
    int y0 = blockIdx.y * 4;

    const float* gbase = g_guide + (size_t)b * CC * HW;

    for (int i = tid; i < 9 * 32 * 32; i += 256) {
        int tap = i >> 10;
        int rem = i & 1023;
        int o  = rem >> 5;
        int cp = rem & 31;
        float w0 = 0.f, w1 = 0.f;
        if (o < KK) {
            w0 = we[(o * CC + 2 * cp) * 9 + tap];
            w1 = we[(o * CC + 2 * cp + 1) * 9 + tap];
        }
        *(__nv_bfloat162*)(smAw + tap * 4096 + off128(o, cp * 4)) =
            __floats2bfloat162_rn(w0, w1);
    }

    for (int i = tid; i < 204 * 32; i += 256) {
        int cp  = i / 204;
        int pos = i - cp * 204;
        int r   = pos / 34;
        int cxl = pos - r * 34;
        int gy = y0 + r - 1;
        int gx = x0 + cxl - 1;
        float v0 = 0.f, v1 = 0.f;
        if (gy >= 0 && gy < HH && gx >= 0 && gx < WW) {
            const float* gp = gbase + (size_t)(2 * cp) * HW + gy * WW + gx;
            v0 = gp[0];
            v1 = gp[HW];
        }
        *(__nv_bfloat162*)(smHt + off128(pos, cp * 4)) = __floats2bfloat162_rn(v0, v1);
    }
    __syncthreads();

    int nbase = wid * 16;
    float acc[2][2][4];
#pragma unroll
    for (int mm = 0; mm < 2; mm++)
#pragma unroll
        for (int nf = 0; nf < 2; nf++)
#pragma unroll
            for (int i = 0; i < 4; i++) acc[mm][nf][i] = 0.f;

#pragma unroll
    for (int tap = 0; tap < 9; tap++) {
        int ty = tap / 3, tx = tap - 3 * ty;
        const char* aw = smAw + tap * 4096;
#pragma unroll
        for (int ks = 0; ks < 4; ks++) {
            int kb0 = ks * 32 + 4 * t;
            int kb1 = kb0 + 16;
            u32 a[2][4];
#pragma unroll
            for (int mm = 0; mm < 2; mm++) {
                int row = mm * 16 + g;
                a[mm][0] = *(const u32*)(aw + off128(row,     kb0));
                a[mm][1] = *(const u32*)(aw + off128(row + 8, kb0));
                a[mm][2] = *(const u32*)(aw + off128(row,     kb1));
                a[mm][3] = *(const u32*)(aw + off128(row + 8, kb1));
            }
            u32 bf[2][2];
#pragma unroll
            for (int nf = 0; nf < 2; nf++) {
                int n = nbase + nf * 8 + g;
                int px = n & 31;
                int py = n >> 5;
                int pos = (py + ty) * 34 + (px + tx);
                bf[nf][0] = *(const u32*)(smHt + off128(pos, kb0));
                bf[nf][1] = *(const u32*)(smHt + off128(pos, kb1));
            }
#pragma unroll
            for (int mm = 0; mm < 2; mm++)
#pragma unroll
                for (int nf = 0; nf < 2; nf++)
                    mma_bf16(acc[mm][nf][0], acc[mm][nf][1],
                             acc[mm][nf][2], acc[mm][nf][3],
                             a[mm][0], a[mm][1], a[mm][2], a[mm][3],
                             bf[nf][0], bf[nf][1]);
        }
    }

#pragma unroll
    for (int mm = 0; mm < 2; mm++) {
        int row = mm * 16 + g;
#pragma unroll
        for (int nf = 0; nf < 2; nf++) {
            int n = nbase + nf * 8 + 2 * t;
            smDs[n * 37 + row]           = acc[mm][nf][0];
            smDs[(n + 1) * 37 + row]     = acc[mm][nf][1];
            smDs[n * 37 + row + 8]       = acc[mm][nf][2];
            smDs[(n + 1) * 37 + row + 8] = acc[mm][nf][3];
        }
    }
    __syncthreads();

    if (tid < 128) {
        int n = tid;
        int px = n & 31;
        int py = n >> 5;
        float a[KK];
        float m = -1e30f;
#pragma unroll
        for (int o = 0; o < KK; o++) {
            a[o] = smDs[n * 37 + o] + be[o];
            m = fmaxf(m, a[o]);
        }
        float s = 0.f;
#pragma unroll
        for (int o = 0; o < KK; o++) {
            a[o] = __expf(a[o] - m);
            s += a[o];
        }
        float inv = 1.f / s;
        float* mb = g_mask + (size_t)b * KK * HW + (y0 + py) * WW + (x0 + px);
#pragma unroll
        for (int o = 0; o < KK; o++) mb[(size_t)o * HW] = a[o] * inv;
    }
}

// ---------------------------------------------------------------------------
// Kernel 3 (v3): CARAFE. X-pair per thread; scalar pred staging (half the
// smem crossbar bytes); 2-way channel split (256 blocks); reflect offsets
// hoisted out of the channel loop.
// ---------------------------------------------------------------------------
#define CCH 8
#define CSPLIT 2
#define CPB (CP / CSPLIT)          // 40 channels per block

__global__ void __launch_bounds__(256)
carafe_kernel(const float* __restrict__ pred,
              float* __restrict__ out) {
    __shared__ float ps[CCH][8][36];

    int zb = blockIdx.z;
    int b  = zb & (BB - 1);
    int cs = zb >> 2;              // 0..CSPLIT-1
    int X0 = blockIdx.x * 64;
    int Y0 = blockIdx.y * 8;
    int lx = threadIdx.x & 31;
    int ly = threadIdx.x >> 5;
    int tid = threadIdx.x;
    int X = X0 + 2 * lx;
    int Y = Y0 + ly;

    // mask pairs for (X, X+1), reused over all 40 channels
    ull m2[KK];
    const float* mb = g_mask + (size_t)b * KK * HW + Y * WW + X;
#pragma unroll
    for (int o = 0; o < KK; o++) {
        float2 mv = *(const float2*)&mb[(size_t)o * HW];
        m2[o] = pack2(mv.x, mv.y);
    }

    int py = ly >> 1;
    int px = lx;
    int yin0 = Y0 / 2 - 2;
    int xin0 = X0 / 2 - 2;

    // hoisted fill coordinates: 9 slots/thread, channel-invariant
    int goff[9];
    int sch[9], sr[9], sc[9];
#pragma unroll
    for (int u = 0; u < 9; u++) {
        int i = u * 256 + tid;          // 0..2303
        int ch = i / 288;
        int r  = (i / 36) % 8;
        int c  = i % 36;
        sch[u] = ch; sr[u] = r; sc[u] = c;
        goff[u] = ch * (PH * PW) + refl(yin0 + r, PH) * PW + refl(xin0 + c, PW);
    }

    const float* pb = pred + (size_t)b * CP * PH * PW + (size_t)cs * CPB * PH * PW;
    float* ob = out + (size_t)b * CP * HW + (size_t)cs * CPB * HW + Y * WW + X;

    for (int cp0 = 0; cp0 < CPB; cp0 += CCH) {
        const float* pchunk = pb + (size_t)cp0 * PH * PW;
#pragma unroll
        for (int u = 0; u < 9; u++)
            ps[sch[u]][sr[u]][sc[u]] = pchunk[goff[u]];
        __syncthreads();

#pragma unroll
        for (int ch = 0; ch < CCH; ch++) {
            ull s2 = 0ULL;
#pragma unroll
            for (int i = 0; i < 5; i++)
#pragma unroll
                for (int j = 0; j < 5; j++) {
                    float p = ps[ch][py + i][px + j];
                    ffma2(s2, pack2(p, p), m2[i * 5 + j]);
                }
            float r0, r1;
            unpack2(s2, r0, r1);
            *(float2*)&ob[(size_t)(cp0 + ch) * HW] = make_float2(r0, r1);
        }
        __syncthreads();
    }
}

extern "C" void kernel_launch(void* const* d_in, const int* in_sizes, int n_in,
                              void* d_out, int out_size) {
    const float* pred = (const float*)d_in[0];
    const float* feat = (const float*)d_in[1];
    const float* wc   = (const float*)d_in[2];
    const float* bc   = (const float*)d_in[3];
    const float* we   = (const float*)d_in[4];
    const float* be   = (const float*)d_in[5];
    float* out = (float*)d_out;

    cudaFuncSetAttribute(compress_mma_kernel,
                         cudaFuncAttributeMaxDynamicSharedMemorySize, CMP_DYN);
    cudaFuncSetAttribute(conv_softmax_mma_kernel,
                         cudaFuncAttributeMaxDynamicSharedMemorySize, CV_DYN);

    compress_mma_kernel<<<dim3(HW / 128, BB), 256, CMP_DYN>>>(feat, wc, bc);
    conv_softmax_mma_kernel<<<dim3(WW / 32, HH / 4, BB), 256, CV_DYN>>>(we, be);
    carafe_kernel<<<dim3(WW / 64, HH / 8, BB * CSPLIT), 256>>>(pred, out);
}

// round 10
// speedup vs baseline: 3.2423x; 1.1000x over previous
#include <cuda_runtime.h>
#include <cuda_bf16.h>

#define BB 4
#define CF 256
#define CC 64
#define HH 128
#define WW 128
#define HW (HH * WW)
#define CP 80
#define PH 64
#define PW 64
#define KS 5
#define KK 25

typedef unsigned long long ull;
typedef unsigned int u32;

// scratch (no allocations allowed)
__device__ __nv_bfloat16 g_guide_px[BB * HW * CC];   // 8.4 MB, [b][pixel][ch]
__device__ float g_mask[BB * KK * HW];               // 6.5 MB

__device__ __forceinline__ int refl(int v, int n) {
    v = (v < 0) ? -v : v;
    v = (v >= n) ? (2 * n - 2 - v) : v;
    return v;
}

__device__ __forceinline__ void ffma2(ull& d, ull a, ull b) {
    asm("fma.rn.f32x2 %0, %1, %2, %3;" : "=l"(d) : "l"(a), "l"(b), "l"(d));
}
__device__ __forceinline__ ull pack2(float x, float y) {
    ull r;
    asm("mov.b64 %0, {%1, %2};" : "=l"(r) : "f"(x), "f"(y));
    return r;
}
__device__ __forceinline__ void unpack2(ull v, float& x, float& y) {
    asm("mov.b64 {%0, %1}, %2;" : "=f"(x), "=f"(y) : "l"(v));
}

__device__ __forceinline__ void mma_bf16(float& c0, float& c1, float& c2, float& c3,
                                         u32 a0, u32 a1, u32 a2, u32 a3,
                                         u32 b0, u32 b1) {
    asm volatile(
        "mma.sync.aligned.m16n8k16.row.col.f32.bf16.bf16.f32 "
        "{%0,%1,%2,%3}, {%4,%5,%6,%7}, {%8,%9}, {%0,%1,%2,%3};"
        : "+f"(c0), "+f"(c1), "+f"(c2), "+f"(c3)
        : "r"(a0), "r"(a1), "r"(a2), "r"(a3), "r"(b0), "r"(b1));
}

// 128B-row XOR swizzle (16B chunks)
__device__ __forceinline__ int off128(int r, int kb) {
    return r * 128 + ((((kb >> 4) ^ (r & 7)) << 4) | (kb & 15));
}

// ---------------------------------------------------------------------------
// Kernel 1 (HMMA): guide[b][m][p] = sum_c wc[m][c]*feat[b][c][p] + bias[m]
// v2: float4 staging + STS.64, single barrier per chunk, bf16 pixel-major out.
// MMA fragment addressing identical to the verified R5 kernel.
// ---------------------------------------------------------------------------
#define CMP_DYN (32768 + 2 * 16384)

__device__ __forceinline__ int a_off(int row, int kbyte) {
    int c = kbyte >> 4;
    return row * 512 + (((c ^ (row & 7)) << 4) | (kbyte & 15));
}
__device__ __forceinline__ int b_off(int n, int kbyte) {
    int c = kbyte >> 4;
    return n * 128 + (((c ^ (n & 7)) << 4) | (kbyte & 15));
}

__device__ __forceinline__ u32 bf2(float x, float y) {
    __nv_bfloat162 v = __floats2bfloat162_rn(x, y);
    return *(u32*)&v;
}

__global__ void __launch_bounds__(256)
compress_mma_kernel(const float* __restrict__ feat,
                    const float* __restrict__ wc,
                    const float* __restrict__ bc) {
    extern __shared__ char dyn[];
    char* smA = dyn;                       // 32KB
    char* smB[2] = { dyn + 32768, dyn + 32768 + 16384 };

    int tid = threadIdx.x;
    int wid = tid >> 5;
    int lane = tid & 31;
    int g = lane >> 2;
    int t = lane & 3;
    int warpM = wid >> 2;
    int warpN = wid & 3;
    int b  = blockIdx.y;
    int n0 = blockIdx.x * 128;

    // ---- stage A (64x256 bf16, swizzled) ----
    for (int q = tid; q < 64 * 128; q += 256) {
        int m = q >> 7, kp = q & 127;
        float2 w = *(const float2*)&wc[m * CF + 2 * kp];
        *(__nv_bfloat162*)(smA + a_off(m, kp * 4)) = __floats2bfloat162_rn(w.x, w.y);
    }

    const float* fbase = feat + (size_t)b * CF * HW + n0;

    // per-chunk staging item: id -> n4 (4 pixels), kq (4 k's). 512 items, u=0..1.
    int n4 = tid & 31;                      // fixed per thread
    int kq0 = tid >> 5;                     // u adds +8

    // ---- stage chunk 0 ----
    {
        char* buf = smB[0];
#pragma unroll
        for (int u = 0; u < 2; u++) {
            int kq = kq0 + u * 8;           // 0..15
            const float* p = fbase + (size_t)(4 * kq) * HW + 4 * n4;
            float4 v0 = *(const float4*)p;
            float4 v1 = *(const float4*)(p + HW);
            float4 v2 = *(const float4*)(p + 2 * HW);
            float4 v3 = *(const float4*)(p + 3 * HW);
            float a0[4] = {v0.x, v0.y, v0.z, v0.w};
            float a1[4] = {v1.x, v1.y, v1.z, v1.w};
            float a2[4] = {v2.x, v2.y, v2.z, v2.w};
            float a3[4] = {v3.x, v3.y, v3.z, v3.w};
#pragma unroll
            for (int j = 0; j < 4; j++) {
                uint2 pr = make_uint2(bf2(a0[j], a1[j]), bf2(a2[j], a3[j]));
                *(uint2*)(buf + b_off(4 * n4 + j, 8 * kq)) = pr;
            }
        }
    }
    __syncthreads();

    float acc[2][4][4];
#pragma unroll
    for (int mm = 0; mm < 2; mm++)
#pragma unroll
        for (int nf = 0; nf < 4; nf++)
#pragma unroll
            for (int i = 0; i < 4; i++) acc[mm][nf][i] = 0.f;

    float4 st[8];

    for (int c = 0; c < 4; c++) {
        // issue next chunk's loads (overlap with MMA below)
        if (c < 3) {
            const float* fc = fbase + (size_t)((c + 1) * 64) * HW;
#pragma unroll
            for (int u = 0; u < 2; u++) {
                int kq = kq0 + u * 8;
                const float* p = fc + (size_t)(4 * kq) * HW + 4 * n4;
                st[u * 4 + 0] = *(const float4*)p;
                st[u * 4 + 1] = *(const float4*)(p + HW);
                st[u * 4 + 2] = *(const float4*)(p + 2 * HW);
                st[u * 4 + 3] = *(const float4*)(p + 3 * HW);
            }
        }

        // compute chunk c (fragment addressing identical to verified R5)
        char* buf = smB[c & 1];
#pragma unroll
        for (int ks = 0; ks < 4; ks++) {
            int kstep = c * 4 + ks;
            u32 a[2][4];
#pragma unroll
            for (int mm = 0; mm < 2; mm++) {
                int row  = warpM * 32 + mm * 16 + g;
                int row8 = row + 8;
                int kb0 = kstep * 32 + 4 * t;
                int kb1 = kb0 + 16;
                a[mm][0] = *(const u32*)(smA + a_off(row,  kb0));
                a[mm][1] = *(const u32*)(smA + a_off(row8, kb0));
                a[mm][2] = *(const u32*)(smA + a_off(row,  kb1));
                a[mm][3] = *(const u32*)(smA + a_off(row8, kb1));
            }
            u32 bf[4][2];
#pragma unroll
            for (int nf = 0; nf < 4; nf++) {
                int n = warpN * 32 + nf * 8 + g;
                int kb0 = ks * 32 + 4 * t;
                bf[nf][0] = *(const u32*)(buf + b_off(n, kb0));
                bf[nf][1] = *(const u32*)(buf + b_off(n, kb0 + 16));
            }
#pragma unroll
            for (int mm = 0; mm < 2; mm++)
#pragma unroll
                for (int nf = 0; nf < 4; nf++)
                    mma_bf16(acc[mm][nf][0], acc[mm][nf][1],
                             acc[mm][nf][2], acc[mm][nf][3],
                             a[mm][0], a[mm][1], a[mm][2], a[mm][3],
                             bf[nf][0], bf[nf][1]);
        }

        // store staged chunk c+1 (other buffer; safe: all warps past sync(c-1))
        if (c < 3) {
            char* nb = smB[(c + 1) & 1];
#pragma unroll
            for (int u = 0; u < 2; u++) {
                int kq = kq0 + u * 8;
                float4 v0 = st[u * 4 + 0], v1 = st[u * 4 + 1];
                float4 v2 = st[u * 4 + 2], v3 = st[u * 4 + 3];
                float a0[4] = {v0.x, v0.y, v0.z, v0.w};
                float a1[4] = {v1.x, v1.y, v1.z, v1.w};
                float a2[4] = {v2.x, v2.y, v2.z, v2.w};
                float a3[4] = {v3.x, v3.y, v3.z, v3.w};
#pragma unroll
                for (int j = 0; j < 4; j++) {
                    uint2 pr = make_uint2(bf2(a0[j], a1[j]), bf2(a2[j], a3[j]));
                    *(uint2*)(nb + b_off(4 * n4 + j, 8 * kq)) = pr;
                }
            }
        }
        __syncthreads();
    }

    // ---- epilogue: transpose to pixel-major bf16 via smem ----
    __nv_bfloat16* T = (__nv_bfloat16*)(dyn + 32768);   // [128 px][68] (pad)
#pragma unroll
    for (int mm = 0; mm < 2; mm++) {
        int row  = warpM * 32 + mm * 16 + g;
        float bias0 = bc[row];
        float bias8 = bc[row + 8];
#pragma unroll
        for (int nf = 0; nf < 4; nf++) {
            int ncol = warpN * 32 + nf * 8 + 2 * t;
            T[ncol * 68 + row]           = __float2bfloat16(acc[mm][nf][0] + bias0);
            T[(ncol + 1) * 68 + row]     = __float2bfloat16(acc[mm][nf][1] + bias0);
            T[ncol * 68 + row + 8]       = __float2bfloat16(acc[mm][nf][2] + bias8);
            T[(ncol + 1) * 68 + row + 8] = __float2bfloat16(acc[mm][nf][3] + bias8);
        }
    }
    __syncthreads();

    u32* gpx = (u32*)g_guide_px + ((size_t)b * HW + n0) * 32;
#pragma unroll
    for (int r = 0; r < 16; r++) {
        int idx = tid + r * 256;        // 0..4095
        int n  = idx >> 5;
        int m2 = idx & 31;
        gpx[n * 32 + m2] = *(u32*)&T[n * 68 + 2 * m2];
    }
}

// ---------------------------------------------------------------------------
// Kernel 2 (HMMA): 3x3 conv as 9 shifted GEMMs + bias + softmax(25).
// v2: halo staged straight from bf16 pixel-major guide (pure u32 copies).
// MMA core identical to verified R7 kernel.
// ---------------------------------------------------------------------------
#define CV_AW_OFF 0
#define CV_HT_OFF 36864
#define CV_DS_OFF (36864 + 26112)
#define CV_DYN    (36864 + 26112 + 128 * 37 * 4)

__global__ void __launch_bounds__(256)
conv_softmax_mma_kernel(const float* __restrict__ we,
                        const float* __restrict__ be) {
    extern __shared__ char dyn[];
    char*  smAw = dyn + CV_AW_OFF;
    char*  smHt = dyn + CV_HT_OFF;
    float* smDs = (float*)(dyn + CV_DS_OFF);

    int tid = threadIdx.x;
    int wid = tid >> 5;
    int lane = tid & 31;
    int g = lane >> 2;
    int t = lane & 3;
    int b  = blockIdx.z;
    int x0 = blockIdx.x * 32;
    int y0 = blockIdx.y * 4;

    // ---- stage weights: Aw[tap][o][c] bf16, rows o>=25 zero ----
    for (int i = tid; i < 9 * 32 * 32; i += 256) {
        int tap = i >> 10;
        int rem = i & 1023;
        int o  = rem >> 5;
        int cp = rem & 31;
        float w0 = 0.f, w1 = 0.f;
        if (o < KK) {
            w0 = we[(o * CC + 2 * cp) * 9 + tap];
            w1 = we[(o * CC + 2 * cp + 1) * 9 + tap];
        }
        *(u32*)(smAw + tap * 4096 + off128(o, cp * 4)) = bf2(w0, w1);
    }

    // ---- stage halo: direct u32 copies from pixel-major bf16 guide ----
    const u32* gpx = (const u32*)g_guide_px + (size_t)b * HW * 32;
    for (int i = tid; i < 204 * 32; i += 256) {
        int pos = i >> 5;
        int cp  = i & 31;
        int r   = pos / 34;
        int cxl = pos - r * 34;
        int gy = y0 + r - 1;
        int gx = x0 + cxl - 1;
        u32 v = 0u;
        if (gy >= 0 && gy < HH && gx >= 0 && gx < WW)
            v = gpx[(gy * WW + gx) * 32 + cp];
        *(u32*)(smHt + off128(pos, cp * 4)) = v;
    }
    __syncthreads();

    int nbase = wid * 16;
    float acc[2][2][4];
#pragma unroll
    for (int mm = 0; mm < 2; mm++)
#pragma unroll
        for (int nf = 0; nf < 2; nf++)
#pragma unroll
            for (int i = 0; i < 4; i++) acc[mm][nf][i] = 0.f;

#pragma unroll
    for (int tap = 0; tap < 9; tap++) {
        int ty = tap / 3, tx = tap - 3 * ty;
        const char* aw = smAw + tap * 4096;
#pragma unroll
        for (int ks = 0; ks < 4; ks++) {
            int kb0 = ks * 32 + 4 * t;
            int kb1 = kb0 + 16;
            u32 a[2][4];
#pragma unroll
            for (int mm = 0; mm < 2; mm++) {
                int row = mm * 16 + g;
                a[mm][0] = *(const u32*)(aw + off128(row,     kb0));
                a[mm][1] = *(const u32*)(aw + off128(row + 8, kb0));
                a[mm][2] = *(const u32*)(aw + off128(row,     kb1));
                a[mm][3] = *(const u32*)(aw + off128(row + 8, kb1));
            }
            u32 bf[2][2];
#pragma unroll
            for (int nf = 0; nf < 2; nf++) {
                int n = nbase + nf * 8 + g;
                int px = n & 31;
                int py = n >> 5;
                int pos = (py + ty) * 34 + (px + tx);
                bf[nf][0] = *(const u32*)(smHt + off128(pos, kb0));
                bf[nf][1] = *(const u32*)(smHt + off128(pos, kb1));
            }
#pragma unroll
            for (int mm = 0; mm < 2; mm++)
#pragma unroll
                for (int nf = 0; nf < 2; nf++)
                    mma_bf16(acc[mm][nf][0], acc[mm][nf][1],
                             acc[mm][nf][2], acc[mm][nf][3],
                             a[mm][0], a[mm][1], a[mm][2], a[mm][3],
                             bf[nf][0], bf[nf][1]);
        }
    }

#pragma unroll
    for (int mm = 0; mm < 2; mm++) {
        int row = mm * 16 + g;
#pragma unroll
        for (int nf = 0; nf < 2; nf++) {
            int n = nbase + nf * 8 + 2 * t;
            smDs[n * 37 + row]           = acc[mm][nf][0];
            smDs[(n + 1) * 37 + row]     = acc[mm][nf][1];
            smDs[n * 37 + row + 8]       = acc[mm][nf][2];
            smDs[(n + 1) * 37 + row + 8] = acc[mm][nf][3];
        }
    }
    __syncthreads();

    if (tid < 128) {
        int n = tid;
        int px = n & 31;
        int py = n >> 5;
        float a[KK];
        float m = -1e30f;
#pragma unroll
        for (int o = 0; o < KK; o++) {
            a[o] = smDs[n * 37 + o] + be[o];
            m = fmaxf(m, a[o]);
        }
        float s = 0.f;
#pragma unroll
        for (int o = 0; o < KK; o++) {
            a[o] = __expf(a[o] - m);
            s += a[o];
        }
        float inv = 1.f / s;
        float* mb = g_mask + (size_t)b * KK * HW + (y0 + py) * WW + (x0 + px);
#pragma unroll
        for (int o = 0; o < KK; o++) mb[(size_t)o * HW] = a[o] * inv;
    }
}

// ---------------------------------------------------------------------------
// Kernel 3 (v3, verified R9): CARAFE. X-pair per thread; scalar staging;
// 2-way channel split; hoisted reflect offsets.
// ---------------------------------------------------------------------------
#define CCH 8
#define CSPLIT 2
#define CPB (CP / CSPLIT)

__global__ void __launch_bounds__(256)
carafe_kernel(const float* __restrict__ pred,
              float* __restrict__ out) {
    __shared__ float ps[CCH][8][36];

    int zb = blockIdx.z;
    int b  = zb & (BB - 1);
    int cs = zb >> 2;
    int X0 = blockIdx.x * 64;
    int Y0 = blockIdx.y * 8;
    int lx = threadIdx.x & 31;
    int ly = threadIdx.x >> 5;
    int tid = threadIdx.x;
    int X = X0 + 2 * lx;
    int Y = Y0 + ly;

    ull m2[KK];
    const float* mb = g_mask + (size_t)b * KK * HW + Y * WW + X;
#pragma unroll
    for (int o = 0; o < KK; o++) {
        float2 mv = *(const float2*)&mb[(size_t)o * HW];
        m2[o] = pack2(mv.x, mv.y);
    }

    int py = ly >> 1;
    int px = lx;
    int yin0 = Y0 / 2 - 2;
    int xin0 = X0 / 2 - 2;

    int goff[9];
    int sch[9], sr[9], sc[9];
#pragma unroll
    for (int u = 0; u < 9; u++) {
        int i = u * 256 + tid;
        int ch = i / 288;
        int r  = (i / 36) % 8;
        int c  = i % 36;
        sch[u] = ch; sr[u] = r; sc[u] = c;
        goff[u] = ch * (PH * PW) + refl(yin0 + r, PH) * PW + refl(xin0 + c, PW);
    }

    const float* pb = pred + (size_t)b * CP * PH * PW + (size_t)cs * CPB * PH * PW;
    float* ob = out + (size_t)b * CP * HW + (size_t)cs * CPB * HW + Y * WW + X;

    for (int cp0 = 0; cp0 < CPB; cp0 += CCH) {
        const float* pchunk = pb + (size_t)cp0 * PH * PW;
#pragma unroll
        for (int u = 0; u < 9; u++)
            ps[sch[u]][sr[u]][sc[u]] = pchunk[goff[u]];
        __syncthreads();

#pragma unroll
        for (int ch = 0; ch < CCH; ch++) {
            ull s2 = 0ULL;
#pragma unroll
            for (int i = 0; i < 5; i++)
#pragma unroll
                for (int j = 0; j < 5; j++) {
                    float p = ps[ch][py + i][px + j];
                    ffma2(s2, pack2(p, p), m2[i * 5 + j]);
                }
            float r0, r1;
            unpack2(s2, r0, r1);
            *(float2*)&ob[(size_t)(cp0 + ch) * HW] = make_float2(r0, r1);
        }
        __syncthreads();
    }
}

extern "C" void kernel_launch(void* const* d_in, const int* in_sizes, int n_in,
                              void* d_out, int out_size) {
    const float* pred = (const float*)d_in[0];
    const float* feat = (const float*)d_in[1];
    const float* wc   = (const float*)d_in[2];
    const float* bc   = (const float*)d_in[3];
    const float* we   = (const float*)d_in[4];
    const float* be   = (const float*)d_in[5];
    float* out = (float*)d_out;

    cudaFuncSetAttribute(compress_mma_kernel,
                         cudaFuncAttributeMaxDynamicSharedMemorySize, CMP_DYN);
    cudaFuncSetAttribute(conv_softmax_mma_kernel,
                         cudaFuncAttributeMaxDynamicSharedMemorySize, CV_DYN);

    compress_mma_kernel<<<dim3(HW / 128, BB), 256, CMP_DYN>>>(feat, wc, bc);
    conv_softmax_mma_kernel<<<dim3(WW / 32, HH / 4, BB), 256, CV_DYN>>>(we, be);
    carafe_kernel<<<dim3(WW / 64, HH / 8, BB * CSPLIT), 256>>>(pred, out);
}

// round 11
// speedup vs baseline: 3.2452x; 1.0009x over previous
#include <cuda_runtime.h>
#include <cuda_bf16.h>

#define BB 4
#define CF 256
#define CC 64
#define HH 128
#define WW 128
#define HW (HH * WW)
#define CP 80
#define PH 64
#define PW 64
#define KS 5
#define KK 25

typedef unsigned long long ull;
typedef unsigned int u32;

// scratch (no allocations allowed)
__device__ __nv_bfloat16 g_guide_px[BB * HW * CC];   // 8.4 MB, [b][pixel][ch]
__device__ float g_mask[BB * KK * HW];               // 6.5 MB

__device__ __forceinline__ int refl(int v, int n) {
    v = (v < 0) ? -v : v;
    v = (v >= n) ? (2 * n - 2 - v) : v;
    return v;
}

__device__ __forceinline__ void ffma2(ull& d, ull a, ull b) {
    asm("fma.rn.f32x2 %0, %1, %2, %3;" : "=l"(d) : "l"(a), "l"(b), "l"(d));
}
__device__ __forceinline__ ull pack2(float x, float y) {
    ull r;
    asm("mov.b64 %0, {%1, %2};" : "=l"(r) : "f"(x), "f"(y));
    return r;
}
__device__ __forceinline__ void unpack2(ull v, float& x, float& y) {
    asm("mov.b64 {%0, %1}, %2;" : "=f"(x), "=f"(y) : "l"(v));
}

__device__ __forceinline__ void mma_bf16(float& c0, float& c1, float& c2, float& c3,
                                         u32 a0, u32 a1, u32 a2, u32 a3,
                                         u32 b0, u32 b1) {
    asm volatile(
        "mma.sync.aligned.m16n8k16.row.col.f32.bf16.bf16.f32 "
        "{%0,%1,%2,%3}, {%4,%5,%6,%7}, {%8,%9}, {%0,%1,%2,%3};"
        : "+f"(c0), "+f"(c1), "+f"(c2), "+f"(c3)
        : "r"(a0), "r"(a1), "r"(a2), "r"(a3), "r"(b0), "r"(b1));
}

// 128B-row XOR swizzle (16B chunks)
__device__ __forceinline__ int off128(int r, int kb) {
    return r * 128 + ((((kb >> 4) ^ (r & 7)) << 4) | (kb & 15));
}

// ---------------------------------------------------------------------------
// Kernel 1 (HMMA, verified R10, 35.4us): guide = wc @ feat + bias
// ---------------------------------------------------------------------------
#define CMP_DYN (32768 + 2 * 16384)

__device__ __forceinline__ int a_off(int row, int kbyte) {
    int c = kbyte >> 4;
    return row * 512 + (((c ^ (row & 7)) << 4) | (kbyte & 15));
}
__device__ __forceinline__ int b_off(int n, int kbyte) {
    int c = kbyte >> 4;
    return n * 128 + (((c ^ (n & 7)) << 4) | (kbyte & 15));
}

__device__ __forceinline__ u32 bf2(float x, float y) {
    __nv_bfloat162 v = __floats2bfloat162_rn(x, y);
    return *(u32*)&v;
}

__global__ void __launch_bounds__(256)
compress_mma_kernel(const float* __restrict__ feat,
                    const float* __restrict__ wc,
                    const float* __restrict__ bc) {
    extern __shared__ char dyn[];
    char* smA = dyn;
    char* smB[2] = { dyn + 32768, dyn + 32768 + 16384 };

    int tid = threadIdx.x;
    int wid = tid >> 5;
    int lane = tid & 31;
    int g = lane >> 2;
    int t = lane & 3;
    int warpM = wid >> 2;
    int warpN = wid & 3;
    int b  = blockIdx.y;
    int n0 = blockIdx.x * 128;

    for (int q = tid; q < 64 * 128; q += 256) {
        int m = q >> 7, kp = q & 127;
        float2 w = *(const float2*)&wc[m * CF + 2 * kp];
        *(__nv_bfloat162*)(smA + a_off(m, kp * 4)) = __floats2bfloat162_rn(w.x, w.y);
    }

    const float* fbase = feat + (size_t)b * CF * HW + n0;
    int n4 = tid & 31;
    int kq0 = tid >> 5;

    {
        char* buf = smB[0];
#pragma unroll
        for (int u = 0; u < 2; u++) {
            int kq = kq0 + u * 8;
            const float* p = fbase + (size_t)(4 * kq) * HW + 4 * n4;
            float4 v0 = *(const float4*)p;
            float4 v1 = *(const float4*)(p + HW);
            float4 v2 = *(const float4*)(p + 2 * HW);
            float4 v3 = *(const float4*)(p + 3 * HW);
            float a0[4] = {v0.x, v0.y, v0.z, v0.w};
            float a1[4] = {v1.x, v1.y, v1.z, v1.w};
            float a2[4] = {v2.x, v2.y, v2.z, v2.w};
            float a3[4] = {v3.x, v3.y, v3.z, v3.w};
#pragma unroll
            for (int j = 0; j < 4; j++) {
                uint2 pr = make_uint2(bf2(a0[j], a1[j]), bf2(a2[j], a3[j]));
                *(uint2*)(buf + b_off(4 * n4 + j, 8 * kq)) = pr;
            }
        }
    }
    __syncthreads();

    float acc[2][4][4];
#pragma unroll
    for (int mm = 0; mm < 2; mm++)
#pragma unroll
        for (int nf = 0; nf < 4; nf++)
#pragma unroll
            for (int i = 0; i < 4; i++) acc[mm][nf][i] = 0.f;

    float4 st[8];

    for (int c = 0; c < 4; c++) {
        if (c < 3) {
            const float* fc = fbase + (size_t)((c + 1) * 64) * HW;
#pragma unroll
            for (int u = 0; u < 2; u++) {
                int kq = kq0 + u * 8;
                const float* p = fc + (size_t)(4 * kq) * HW + 4 * n4;
                st[u * 4 + 0] = *(const float4*)p;
                st[u * 4 + 1] = *(const float4*)(p + HW);
                st[u * 4 + 2] = *(const float4*)(p + 2 * HW);
                st[u * 4 + 3] = *(const float4*)(p + 3 * HW);
            }
        }

        char* buf = smB[c & 1];
#pragma unroll
        for (int ks = 0; ks < 4; ks++) {
            int kstep = c * 4 + ks;
            u32 a[2][4];
#pragma unroll
            for (int mm = 0; mm < 2; mm++) {
                int row  = warpM * 32 + mm * 16 + g;
                int row8 = row + 8;
                int kb0 = kstep * 32 + 4 * t;
                int kb1 = kb0 + 16;
                a[mm][0] = *(const u32*)(smA + a_off(row,  kb0));
                a[mm][1] = *(const u32*)(smA + a_off(row8, kb0));
                a[mm][2] = *(const u32*)(smA + a_off(row,  kb1));
                a[mm][3] = *(const u32*)(smA + a_off(row8, kb1));
            }
            u32 bf[4][2];
#pragma unroll
            for (int nf = 0; nf < 4; nf++) {
                int n = warpN * 32 + nf * 8 + g;
                int kb0 = ks * 32 + 4 * t;
                bf[nf][0] = *(const u32*)(buf + b_off(n, kb0));
                bf[nf][1] = *(const u32*)(buf + b_off(n, kb0 + 16));
            }
#pragma unroll
            for (int mm = 0; mm < 2; mm++)
#pragma unroll
                for (int nf = 0; nf < 4; nf++)
                    mma_bf16(acc[mm][nf][0], acc[mm][nf][1],
                             acc[mm][nf][2], acc[mm][nf][3],
                             a[mm][0], a[mm][1], a[mm][2], a[mm][3],
                             bf[nf][0], bf[nf][1]);
        }

        if (c < 3) {
            char* nb = smB[(c + 1) & 1];
#pragma unroll
            for (int u = 0; u < 2; u++) {
                int kq = kq0 + u * 8;
                float4 v0 = st[u * 4 + 0], v1 = st[u * 4 + 1];
                float4 v2 = st[u * 4 + 2], v3 = st[u * 4 + 3];
                float a0[4] = {v0.x, v0.y, v0.z, v0.w};
                float a1[4] = {v1.x, v1.y, v1.z, v1.w};
                float a2[4] = {v2.x, v2.y, v2.z, v2.w};
                float a3[4] = {v3.x, v3.y, v3.z, v3.w};
#pragma unroll
                for (int j = 0; j < 4; j++) {
                    uint2 pr = make_uint2(bf2(a0[j], a1[j]), bf2(a2[j], a3[j]));
                    *(uint2*)(nb + b_off(4 * n4 + j, 8 * kq)) = pr;
                }
            }
        }
        __syncthreads();
    }

    __nv_bfloat16* T = (__nv_bfloat16*)(dyn + 32768);
#pragma unroll
    for (int mm = 0; mm < 2; mm++) {
        int row  = warpM * 32 + mm * 16 + g;
        float bias0 = bc[row];
        float bias8 = bc[row + 8];
#pragma unroll
        for (int nf = 0; nf < 4; nf++) {
            int ncol = warpN * 32 + nf * 8 + 2 * t;
            T[ncol * 68 + row]           = __float2bfloat16(acc[mm][nf][0] + bias0);
            T[(ncol + 1) * 68 + row]     = __float2bfloat16(acc[mm][nf][1] + bias0);
            T[ncol * 68 + row + 8]       = __float2bfloat16(acc[mm][nf][2] + bias8);
            T[(ncol + 1) * 68 + row + 8] = __float2bfloat16(acc[mm][nf][3] + bias8);
        }
    }
    __syncthreads();

    u32* gpx = (u32*)g_guide_px + ((size_t)b * HW + n0) * 32;
#pragma unroll
    for (int r = 0; r < 16; r++) {
        int idx = tid + r * 256;
        int n  = idx >> 5;
        int m2 = idx & 31;
        gpx[n * 32 + m2] = *(u32*)&T[n * 68 + 2 * m2];
    }
}

// ---------------------------------------------------------------------------
// Kernel 2 (HMMA, verified R10): 3x3 conv + bias + softmax(25)
// ---------------------------------------------------------------------------
#define CV_AW_OFF 0
#define CV_HT_OFF 36864
#define CV_DS_OFF (36864 + 26112)
#define CV_DYN    (36864 + 26112 + 128 * 37 * 4)

__global__ void __launch_bounds__(256)
conv_softmax_mma_kernel(const float* __restrict__ we,
                        const float* __restrict__ be) {
    extern __shared__ char dyn[];
    char*  smAw = dyn + CV_AW_OFF;
    char*  smHt = dyn + CV_HT_OFF;
    float* smDs = (float*)(dyn + CV_DS_OFF);

    int tid = threadIdx.x;
    int wid = tid >> 5;
    int lane = tid & 31;
    int g = lane >> 2;
    int t = lane & 3;
    int b  = blockIdx.z;
    int x0 = blockIdx.x * 32;
    int y0 = blockIdx.y * 4;

    for (int i = tid; i < 9 * 32 * 32; i += 256) {
        int tap = i >> 10;
        int rem = i & 1023;
        int o  = rem >> 5;
        int cp = rem & 31;
        float w0 = 0.f, w1 = 0.f;
        if (o < KK) {
            w0 = we[(o * CC + 2 * cp) * 9 + tap];
            w1 = we[(o * CC + 2 * cp + 1) * 9 + tap];
        }
        *(u32*)(smAw + tap * 4096 + off128(o, cp * 4)) = bf2(w0, w1);
    }

    const u32* gpx = (const u32*)g_guide_px + (size_t)b * HW * 32;
    for (int i = tid; i < 204 * 32; i += 256) {
        int pos = i >> 5;
        int cp  = i & 31;
        int r   = pos / 34;
        int cxl = pos - r * 34;
        int gy = y0 + r - 1;
        int gx = x0 + cxl - 1;
        u32 v = 0u;
        if (gy >= 0 && gy < HH && gx >= 0 && gx < WW)
            v = gpx[(gy * WW + gx) * 32 + cp];
        *(u32*)(smHt + off128(pos, cp * 4)) = v;
    }
    __syncthreads();

    int nbase = wid * 16;
    float acc[2][2][4];
#pragma unroll
    for (int mm = 0; mm < 2; mm++)
#pragma unroll
        for (int nf = 0; nf < 2; nf++)
#pragma unroll
            for (int i = 0; i < 4; i++) acc[mm][nf][i] = 0.f;

#pragma unroll
    for (int tap = 0; tap < 9; tap++) {
        int ty = tap / 3, tx = tap - 3 * ty;
        const char* aw = smAw + tap * 4096;
#pragma unroll
        for (int ks = 0; ks < 4; ks++) {
            int kb0 = ks * 32 + 4 * t;
            int kb1 = kb0 + 16;
            u32 a[2][4];
#pragma unroll
            for (int mm = 0; mm < 2; mm++) {
                int row = mm * 16 + g;
                a[mm][0] = *(const u32*)(aw + off128(row,     kb0));
                a[mm][1] = *(const u32*)(aw + off128(row + 8, kb0));
                a[mm][2] = *(const u32*)(aw + off128(row,     kb1));
                a[mm][3] = *(const u32*)(aw + off128(row + 8, kb1));
            }
            u32 bf[2][2];
#pragma unroll
            for (int nf = 0; nf < 2; nf++) {
                int n = nbase + nf * 8 + g;
                int px = n & 31;
                int py = n >> 5;
                int pos = (py + ty) * 34 + (px + tx);
                bf[nf][0] = *(const u32*)(smHt + off128(pos, kb0));
                bf[nf][1] = *(const u32*)(smHt + off128(pos, kb1));
            }
#pragma unroll
            for (int mm = 0; mm < 2; mm++)
#pragma unroll
                for (int nf = 0; nf < 2; nf++)
                    mma_bf16(acc[mm][nf][0], acc[mm][nf][1],
                             acc[mm][nf][2], acc[mm][nf][3],
                             a[mm][0], a[mm][1], a[mm][2], a[mm][3],
                             bf[nf][0], bf[nf][1]);
        }
    }

#pragma unroll
    for (int mm = 0; mm < 2; mm++) {
        int row = mm * 16 + g;
#pragma unroll
        for (int nf = 0; nf < 2; nf++) {
            int n = nbase + nf * 8 + 2 * t;
            smDs[n * 37 + row]           = acc[mm][nf][0];
            smDs[(n + 1) * 37 + row]     = acc[mm][nf][1];
            smDs[n * 37 + row + 8]       = acc[mm][nf][2];
            smDs[(n + 1) * 37 + row + 8] = acc[mm][nf][3];
        }
    }
    __syncthreads();

    if (tid < 128) {
        int n = tid;
        int px = n & 31;
        int py = n >> 5;
        float a[KK];
        float m = -1e30f;
#pragma unroll
        for (int o = 0; o < KK; o++) {
            a[o] = smDs[n * 37 + o] + be[o];
            m = fmaxf(m, a[o]);
        }
        float s = 0.f;
#pragma unroll
        for (int o = 0; o < KK; o++) {
            a[o] = __expf(a[o] - m);
            s += a[o];
        }
        float inv = 1.f / s;
        float* mb = g_mask + (size_t)b * KK * HW + (y0 + py) * WW + (x0 + px);
#pragma unroll
        for (int o = 0; o < KK; o++) mb[(size_t)o * HW] = a[o] * inv;
    }
}

// ---------------------------------------------------------------------------
// Kernel 3 (v4): CARAFE with double-buffered pred tiles + software pipeline.
// Chunk c+1's 9 LDGs issue before compute(c); STS to alternate buffer after;
// ONE barrier per chunk (was 2). Rest identical to verified R9/R10 version.
// ---------------------------------------------------------------------------
#define CCH 8
#define CSPLIT 2
#define CPB (CP / CSPLIT)
#define NCHUNK (CPB / CCH)         // 5

__global__ void __launch_bounds__(256)
carafe_kernel(const float* __restrict__ pred,
              float* __restrict__ out) {
    __shared__ float ps[2][CCH][8][36];

    int zb = blockIdx.z;
    int b  = zb & (BB - 1);
    int cs = zb >> 2;
    int X0 = blockIdx.x * 64;
    int Y0 = blockIdx.y * 8;
    int lx = threadIdx.x & 31;
    int ly = threadIdx.x >> 5;
    int tid = threadIdx.x;
    int X = X0 + 2 * lx;
    int Y = Y0 + ly;

    ull m2[KK];
    const float* mb = g_mask + (size_t)b * KK * HW + Y * WW + X;
#pragma unroll
    for (int o = 0; o < KK; o++) {
        float2 mv = *(const float2*)&mb[(size_t)o * HW];
        m2[o] = pack2(mv.x, mv.y);
    }

    int py = ly >> 1;
    int px = lx;
    int yin0 = Y0 / 2 - 2;
    int xin0 = X0 / 2 - 2;

    int goff[9];
    int sch[9], sr[9], sc[9];
#pragma unroll
    for (int u = 0; u < 9; u++) {
        int i = u * 256 + tid;
        int ch = i / 288;
        int r  = (i / 36) % 8;
        int c  = i % 36;
        sch[u] = ch; sr[u] = r; sc[u] = c;
        goff[u] = ch * (PH * PW) + refl(yin0 + r, PH) * PW + refl(xin0 + c, PW);
    }

    const float* pb = pred + (size_t)b * CP * PH * PW + (size_t)cs * CPB * PH * PW;
    float* ob = out + (size_t)b * CP * HW + (size_t)cs * CPB * HW + Y * WW + X;

    // prologue: stage chunk 0 into buffer 0
    {
        float r[9];
#pragma unroll
        for (int u = 0; u < 9; u++) r[u] = pb[goff[u]];
#pragma unroll
        for (int u = 0; u < 9; u++) ps[0][sch[u]][sr[u]][sc[u]] = r[u];
    }
    __syncthreads();

    float rnext[9];
    for (int c = 0; c < NCHUNK; c++) {
        // issue next chunk's loads early (overlap with compute below)
        if (c < NCHUNK - 1) {
            const float* pn = pb + (size_t)(c + 1) * CCH * PH * PW;
#pragma unroll
            for (int u = 0; u < 9; u++) rnext[u] = pn[goff[u]];
        }

        // compute chunk c from buffer c&1
        const float (*cur)[8][36] = ps[c & 1];
        int cp0 = c * CCH;
#pragma unroll
        for (int ch = 0; ch < CCH; ch++) {
            ull s2 = 0ULL;
#pragma unroll
            for (int i = 0; i < 5; i++)
#pragma unroll
                for (int j = 0; j < 5; j++) {
                    float p = cur[ch][py + i][px + j];
                    ffma2(s2, pack2(p, p), m2[i * 5 + j]);
                }
            float r0, r1;
            unpack2(s2, r0, r1);
            *(float2*)&ob[(size_t)(cp0 + ch) * HW] = make_float2(r0, r1);
        }

        // store staged chunk c+1 into the other buffer
        if (c < NCHUNK - 1) {
#pragma unroll
            for (int u = 0; u < 9; u++)
                ps[(c + 1) & 1][sch[u]][sr[u]][sc[u]] = rnext[u];
        }
        __syncthreads();
    }
}

extern "C" void kernel_launch(void* const* d_in, const int* in_sizes, int n_in,
                              void* d_out, int out_size) {
    const float* pred = (const float*)d_in[0];
    const float* feat = (const float*)d_in[1];
    const float* wc   = (const float*)d_in[2];
    const float* bc   = (const float*)d_in[3];
    const float* we   = (const float*)d_in[4];
    const float* be   = (const float*)d_in[5];
    float* out = (float*)d_out;

    cudaFuncSetAttribute(compress_mma_kernel,
                         cudaFuncAttributeMaxDynamicSharedMemorySize, CMP_DYN);
    cudaFuncSetAttribute(conv_softmax_mma_kernel,
                         cudaFuncAttributeMaxDynamicSharedMemorySize, CV_DYN);

    compress_mma_kernel<<<dim3(HW / 128, BB), 256, CMP_DYN>>>(feat, wc, bc);
    conv_softmax_mma_kernel<<<dim3(WW / 32, HH / 4, BB), 256, CV_DYN>>>(we, be);
    carafe_kernel<<<dim3(WW / 64, HH / 8, BB * CSPLIT), 256>>>(pred, out);
}